// round 1
// baseline (speedup 1.0000x reference)
#include <cuda_runtime.h>
#include <math.h>

#define BTN 16384   // B*T
#define FN  32      // features
#define HN  256     // hidden
#define FHN 8192    // F*H

// Scratch (allocation-free contract: __device__ globals)
__device__ float g_h1 [(size_t)BTN * FN * HN];   // [f][bt][h]  536MB
__device__ float g_stk[(size_t)BTN * FN * HN];   // [bt][f][h]  536MB (pre-LN then LN'd in place)
__device__ float g_sh [(size_t)BTN * HN];        // 16MB
__device__ float g_sres[BTN * FN];               // 2MB
__device__ float g_wts [BTN * FN];               // 2MB

__device__ __forceinline__ float eluf(float z) { return z > 0.f ? z : (expf(z) - 1.f); }
__device__ __forceinline__ float sigf(float z) { return 1.f / (1.f + expf(-z)); }

// ---------------------------------------------------------------------------
// Stage A: per feature f, h1 = ELU(x_f * w1[f] + b1[f]) @ w2[f] + b2[f]
// GEMM 16384 x 256 x 256, A generated on the fly. Tile 128x128x8, 256 thr.
// ---------------------------------------------------------------------------
__global__ __launch_bounds__(256) void k_stageA(
    const float* __restrict__ x,  const float* __restrict__ w1, const float* __restrict__ b1,
    const float* __restrict__ w2, const float* __restrict__ b2)
{
    const int f  = blockIdx.z;
    const int m0 = blockIdx.y * 128;
    const int n0 = blockIdx.x * 128;
    __shared__ float As[8][128];
    __shared__ float Bs[8][128];
    const int tid  = threadIdx.x;
    const int tx   = tid & 15, ty = tid >> 4;
    const int aRow = tid >> 1, aCol = (tid & 1) << 2;
    const int bRow = tid >> 5, bCol = (tid & 31) << 2;
    const float* __restrict__ w2f = w2 + (size_t)f * HN * HN;
    const float xv = x[(m0 + aRow) * FN + f];

    float acc[8][8];
#pragma unroll
    for (int i = 0; i < 8; i++)
#pragma unroll
        for (int j = 0; j < 8; j++) acc[i][j] = 0.f;

    for (int k0 = 0; k0 < HN; k0 += 8) {
        float4 wv = *(const float4*)(w1 + f * HN + k0 + aCol);
        float4 bv = *(const float4*)(b1 + f * HN + k0 + aCol);
        As[aCol + 0][aRow] = eluf(xv * wv.x + bv.x);
        As[aCol + 1][aRow] = eluf(xv * wv.y + bv.y);
        As[aCol + 2][aRow] = eluf(xv * wv.z + bv.z);
        As[aCol + 3][aRow] = eluf(xv * wv.w + bv.w);
        *(float4*)&Bs[bRow][bCol] =
            *(const float4*)(w2f + (size_t)(k0 + bRow) * HN + n0 + bCol);
        __syncthreads();
#pragma unroll
        for (int kk = 0; kk < 8; kk++) {
            float4 a0 = *(const float4*)&As[kk][ty * 4];
            float4 a1 = *(const float4*)&As[kk][64 + ty * 4];
            float4 c0 = *(const float4*)&Bs[kk][tx * 4];
            float4 c1 = *(const float4*)&Bs[kk][64 + tx * 4];
            float ar[8] = {a0.x, a0.y, a0.z, a0.w, a1.x, a1.y, a1.z, a1.w};
            float br[8] = {c0.x, c0.y, c0.z, c0.w, c1.x, c1.y, c1.z, c1.w};
#pragma unroll
            for (int i = 0; i < 8; i++)
#pragma unroll
                for (int j = 0; j < 8; j++) acc[i][j] += ar[i] * br[j];
        }
        __syncthreads();
    }
#pragma unroll
    for (int ih = 0; ih < 2; ih++)
#pragma unroll
        for (int i = 0; i < 4; i++) {
            const int m = m0 + ih * 64 + ty * 4 + i;
            const size_t rb = ((size_t)f * BTN + m) * HN;
#pragma unroll
            for (int jh = 0; jh < 2; jh++) {
                const int n = n0 + jh * 64 + tx * 4;
                float4 b2v = *(const float4*)(b2 + f * HN + n);
                float4 o;
                o.x = acc[ih * 4 + i][jh * 4 + 0] + b2v.x;
                o.y = acc[ih * 4 + i][jh * 4 + 1] + b2v.y;
                o.z = acc[ih * 4 + i][jh * 4 + 2] + b2v.z;
                o.w = acc[ih * 4 + i][jh * 4 + 3] + b2v.w;
                *(float4*)(g_h1 + rb + n) = o;
            }
        }
}

// ---------------------------------------------------------------------------
// Stage B: per feature f, dual GEMM (wg, wf) sharing A = h1_f, fused GLU +
// skip residual. Writes pre-LN values into g_stk[bt][f][h].
// Tile 128x64x8, 256 thr, 8x4 per-thread per GEMM.
// ---------------------------------------------------------------------------
__global__ __launch_bounds__(256) void k_stageB(
    const float* __restrict__ x,
    const float* __restrict__ wg, const float* __restrict__ bg,
    const float* __restrict__ wf, const float* __restrict__ bf,
    const float* __restrict__ ws, const float* __restrict__ bs)
{
    const int f  = blockIdx.z;
    const int m0 = blockIdx.y * 128;
    const int n0 = blockIdx.x * 64;
    __shared__ float As[8][128];
    __shared__ float Bgs[8][64];
    __shared__ float Bvs[8][64];
    const int tid  = threadIdx.x;
    const int tx   = tid & 15, ty = tid >> 4;
    const int aRow = tid >> 1, aCol = (tid & 1) << 2;
    const int bRow = tid >> 5, bCol = (tid & 31) << 1;
    const float* __restrict__ A   = g_h1 + (size_t)f * BTN * HN;
    const float* __restrict__ wgf = wg + (size_t)f * HN * HN;
    const float* __restrict__ wff = wf + (size_t)f * HN * HN;

    float accg[8][4], accv[8][4];
#pragma unroll
    for (int i = 0; i < 8; i++)
#pragma unroll
        for (int j = 0; j < 4; j++) { accg[i][j] = 0.f; accv[i][j] = 0.f; }

    for (int k0 = 0; k0 < HN; k0 += 8) {
        float4 av = *(const float4*)(A + (size_t)(m0 + aRow) * HN + k0 + aCol);
        As[aCol + 0][aRow] = av.x;
        As[aCol + 1][aRow] = av.y;
        As[aCol + 2][aRow] = av.z;
        As[aCol + 3][aRow] = av.w;
        *(float2*)&Bgs[bRow][bCol] =
            *(const float2*)(wgf + (size_t)(k0 + bRow) * HN + n0 + bCol);
        *(float2*)&Bvs[bRow][bCol] =
            *(const float2*)(wff + (size_t)(k0 + bRow) * HN + n0 + bCol);
        __syncthreads();
#pragma unroll
        for (int kk = 0; kk < 8; kk++) {
            float4 a0 = *(const float4*)&As[kk][ty * 4];
            float4 a1 = *(const float4*)&As[kk][64 + ty * 4];
            float4 g4 = *(const float4*)&Bgs[kk][tx * 4];
            float4 v4 = *(const float4*)&Bvs[kk][tx * 4];
            float ar[8]  = {a0.x, a0.y, a0.z, a0.w, a1.x, a1.y, a1.z, a1.w};
            float brg[4] = {g4.x, g4.y, g4.z, g4.w};
            float brv[4] = {v4.x, v4.y, v4.z, v4.w};
#pragma unroll
            for (int i = 0; i < 8; i++)
#pragma unroll
                for (int j = 0; j < 4; j++) {
                    accg[i][j] += ar[i] * brg[j];
                    accv[i][j] += ar[i] * brv[j];
                }
        }
        __syncthreads();
    }
    const int n = n0 + tx * 4;
    float4 bgv = *(const float4*)(bg + f * HN + n);
    float4 bfv = *(const float4*)(bf + f * HN + n);
    float4 wsv = *(const float4*)(ws + f * HN + n);
    float4 bsv = *(const float4*)(bs + f * HN + n);
#pragma unroll
    for (int ih = 0; ih < 2; ih++)
#pragma unroll
        for (int i = 0; i < 4; i++) {
            const int m = m0 + ih * 64 + ty * 4 + i;
            const float xv = x[m * FN + f];
            const int r = ih * 4 + i;
            float4 o;
            o.x = sigf(accg[r][0] + bgv.x) * (accv[r][0] + bfv.x) + xv * wsv.x + bsv.x;
            o.y = sigf(accg[r][1] + bgv.y) * (accv[r][1] + bfv.y) + xv * wsv.y + bsv.y;
            o.z = sigf(accg[r][2] + bgv.z) * (accv[r][2] + bfv.z) + xv * wsv.z + bsv.z;
            o.w = sigf(accg[r][3] + bgv.w) * (accv[r][3] + bfv.w) + xv * wsv.w + bsv.w;
            *(float4*)(g_stk + (size_t)m * FHN + f * HN + n) = o;
        }
}

// ---------------------------------------------------------------------------
// LayerNorm over H=256 per (bt, f) row, in place. One warp per row.
// ---------------------------------------------------------------------------
__global__ __launch_bounds__(256) void k_ln(
    const float* __restrict__ gamma, const float* __restrict__ beta)
{
    const int lane = threadIdx.x & 31;
    const int row  = blockIdx.x * 8 + (threadIdx.x >> 5);   // bt*F + f
    const int f    = row & (FN - 1);
    float* __restrict__ p = g_stk + (size_t)row * HN;
    float v[8];
    float s = 0.f;
#pragma unroll
    for (int i = 0; i < 8; i++) { v[i] = p[i * 32 + lane]; s += v[i]; }
#pragma unroll
    for (int o = 16; o > 0; o >>= 1) s += __shfl_xor_sync(0xffffffffu, s, o);
    const float mean = s * (1.f / 256.f);
    float q = 0.f;
#pragma unroll
    for (int i = 0; i < 8; i++) { float d = v[i] - mean; q += d * d; }
#pragma unroll
    for (int o = 16; o > 0; o >>= 1) q += __shfl_xor_sync(0xffffffffu, q, o);
    const float rstd = rsqrtf(q * (1.f / 256.f) + 1e-5f);
#pragma unroll
    for (int i = 0; i < 8; i++) {
        const int h = i * 32 + lane;
        p[h] = (v[i] - mean) * rstd * gamma[f * HN + h] + beta[f * HN + h];
    }
}

// ---------------------------------------------------------------------------
// Selection GEMM: sh = ELU(flat(16384x8192) @ sw1(8192x256) + sb1)
// Tile 128x128x8.
// ---------------------------------------------------------------------------
__global__ __launch_bounds__(256) void k_selgemm(
    const float* __restrict__ sw1, const float* __restrict__ sb1)
{
    const int m0 = blockIdx.y * 128;
    const int n0 = blockIdx.x * 128;
    __shared__ float As[8][128];
    __shared__ float Bs[8][128];
    const int tid  = threadIdx.x;
    const int tx   = tid & 15, ty = tid >> 4;
    const int aRow = tid >> 1, aCol = (tid & 1) << 2;
    const int bRow = tid >> 5, bCol = (tid & 31) << 2;

    float acc[8][8];
#pragma unroll
    for (int i = 0; i < 8; i++)
#pragma unroll
        for (int j = 0; j < 8; j++) acc[i][j] = 0.f;

    for (int k0 = 0; k0 < FHN; k0 += 8) {
        float4 av = *(const float4*)(g_stk + (size_t)(m0 + aRow) * FHN + k0 + aCol);
        As[aCol + 0][aRow] = av.x;
        As[aCol + 1][aRow] = av.y;
        As[aCol + 2][aRow] = av.z;
        As[aCol + 3][aRow] = av.w;
        *(float4*)&Bs[bRow][bCol] =
            *(const float4*)(sw1 + (size_t)(k0 + bRow) * HN + n0 + bCol);
        __syncthreads();
#pragma unroll
        for (int kk = 0; kk < 8; kk++) {
            float4 a0 = *(const float4*)&As[kk][ty * 4];
            float4 a1 = *(const float4*)&As[kk][64 + ty * 4];
            float4 c0 = *(const float4*)&Bs[kk][tx * 4];
            float4 c1 = *(const float4*)&Bs[kk][64 + tx * 4];
            float ar[8] = {a0.x, a0.y, a0.z, a0.w, a1.x, a1.y, a1.z, a1.w};
            float br[8] = {c0.x, c0.y, c0.z, c0.w, c1.x, c1.y, c1.z, c1.w};
#pragma unroll
            for (int i = 0; i < 8; i++)
#pragma unroll
                for (int j = 0; j < 8; j++) acc[i][j] += ar[i] * br[j];
        }
        __syncthreads();
    }
#pragma unroll
    for (int ih = 0; ih < 2; ih++)
#pragma unroll
        for (int i = 0; i < 4; i++) {
            const int m = m0 + ih * 64 + ty * 4 + i;
#pragma unroll
            for (int jh = 0; jh < 2; jh++) {
                const int n = n0 + jh * 64 + tx * 4;
                float4 bb = *(const float4*)(sb1 + n);
                float4 o;
                o.x = eluf(acc[ih * 4 + i][jh * 4 + 0] + bb.x);
                o.y = eluf(acc[ih * 4 + i][jh * 4 + 1] + bb.y);
                o.z = eluf(acc[ih * 4 + i][jh * 4 + 2] + bb.z);
                o.w = eluf(acc[ih * 4 + i][jh * 4 + 3] + bb.w);
                *(float4*)(g_sh + (size_t)m * HN + n) = o;
            }
        }
}

// ---------------------------------------------------------------------------
// sres = flat @ ssw(8192x32) + ssb. One warp per token, lane = output col.
// ---------------------------------------------------------------------------
__global__ __launch_bounds__(256) void k_sres(
    const float* __restrict__ ssw, const float* __restrict__ ssb)
{
    const int lane = threadIdx.x & 31;
    const int m    = blockIdx.x * 8 + (threadIdx.x >> 5);
    const float* __restrict__ a = g_stk + (size_t)m * FHN;
    float acc = 0.f;
#pragma unroll 4
    for (int k = 0; k < FHN; k += 4) {
        float4 av = *(const float4*)(a + k);
        acc += av.x * ssw[(k + 0) * FN + lane];
        acc += av.y * ssw[(k + 1) * FN + lane];
        acc += av.z * ssw[(k + 2) * FN + lane];
        acc += av.w * ssw[(k + 3) * FN + lane];
    }
    g_sres[m * FN + lane] = acc + ssb[lane];
}

// ---------------------------------------------------------------------------
// Small selection tail: sh2 = sh@sw2+sb2; sglu; + sres; LN(32); softmax.
// One warp per token, lane = feature index.
// ---------------------------------------------------------------------------
__global__ __launch_bounds__(256) void k_sel(
    const float* __restrict__ sw2, const float* __restrict__ sb2,
    const float* __restrict__ swg, const float* __restrict__ sbg,
    const float* __restrict__ swf, const float* __restrict__ sbf,
    const float* __restrict__ sgm, const float* __restrict__ sbt)
{
    const int lane = threadIdx.x & 31;
    const int m    = blockIdx.x * 8 + (threadIdx.x >> 5);
    const float* __restrict__ sh = g_sh + (size_t)m * HN;
    float shv[8];
#pragma unroll
    for (int i = 0; i < 8; i++) shv[i] = sh[i * 32 + lane];
    float acc = sb2[lane];
#pragma unroll 8
    for (int h = 0; h < HN; h++) {
        float s = __shfl_sync(0xffffffffu, shv[h >> 5], h & 31);
        acc += s * sw2[h * FN + lane];
    }
    float ag = sbg[lane], af = sbf[lane];
#pragma unroll
    for (int i = 0; i < FN; i++) {
        float s = __shfl_sync(0xffffffffu, acc, i);
        ag += s * swg[i * FN + lane];
        af += s * swf[i * FN + lane];
    }
    const float pre = g_sres[m * FN + lane] + sigf(ag) * af;
    float s1 = pre;
#pragma unroll
    for (int o = 16; o > 0; o >>= 1) s1 += __shfl_xor_sync(0xffffffffu, s1, o);
    const float mean = s1 * (1.f / 32.f);
    const float d = pre - mean;
    float q = d * d;
#pragma unroll
    for (int o = 16; o > 0; o >>= 1) q += __shfl_xor_sync(0xffffffffu, q, o);
    const float y = d * rsqrtf(q * (1.f / 32.f) + 1e-5f) * sgm[lane] + sbt[lane];
    float mx = y;
#pragma unroll
    for (int o = 16; o > 0; o >>= 1) mx = fmaxf(mx, __shfl_xor_sync(0xffffffffu, mx, o));
    const float e = expf(y - mx);
    float se = e;
#pragma unroll
    for (int o = 16; o > 0; o >>= 1) se += __shfl_xor_sync(0xffffffffu, se, o);
    g_wts[m * FN + lane] = e / se;
}

// ---------------------------------------------------------------------------
// out[bt,h] = sum_f stacked[bt,f,h] * weights[bt,f]. Memory-bound pass.
// ---------------------------------------------------------------------------
__global__ __launch_bounds__(256) void k_out(float* __restrict__ out)
{
    const int m = blockIdx.x * 4 + (threadIdx.x >> 6);
    const int c = threadIdx.x & 63;   // float4 chunk of H
    const float4* __restrict__ sp = (const float4*)(g_stk + (size_t)m * FHN);
    const float* __restrict__ wp = g_wts + m * FN;
    float4 acc = make_float4(0.f, 0.f, 0.f, 0.f);
#pragma unroll
    for (int f = 0; f < FN; f++) {
        const float w = wp[f];
        float4 v = sp[f * 64 + c];
        acc.x += w * v.x; acc.y += w * v.y; acc.z += w * v.z; acc.w += w * v.w;
    }
    ((float4*)out)[(size_t)m * 64 + c] = acc;
}

// ---------------------------------------------------------------------------
extern "C" void kernel_launch(void* const* d_in, const int* in_sizes, int n_in,
                              void* d_out, int out_size)
{
    const float* x    = (const float*)d_in[0];
    const float* w1   = (const float*)d_in[1];
    const float* b1   = (const float*)d_in[2];
    const float* w2   = (const float*)d_in[3];
    const float* b2   = (const float*)d_in[4];
    const float* wg   = (const float*)d_in[5];
    const float* bg   = (const float*)d_in[6];
    const float* wf   = (const float*)d_in[7];
    const float* bf   = (const float*)d_in[8];
    const float* gamma= (const float*)d_in[9];
    const float* beta = (const float*)d_in[10];
    const float* ws   = (const float*)d_in[11];
    const float* bs   = (const float*)d_in[12];
    const float* sw1  = (const float*)d_in[13];
    const float* sb1  = (const float*)d_in[14];
    const float* sw2  = (const float*)d_in[15];
    const float* sb2  = (const float*)d_in[16];
    const float* swg  = (const float*)d_in[17];
    const float* sbg  = (const float*)d_in[18];
    const float* swf  = (const float*)d_in[19];
    const float* sbf  = (const float*)d_in[20];
    const float* sgm  = (const float*)d_in[21];
    const float* sbt  = (const float*)d_in[22];
    const float* ssw  = (const float*)d_in[23];
    const float* ssb  = (const float*)d_in[24];
    float* out = (float*)d_out;

    k_stageA <<<dim3(2, 128, 32), 256>>>(x, w1, b1, w2, b2);
    k_stageB <<<dim3(4, 128, 32), 256>>>(x, wg, bg, wf, bf, ws, bs);
    k_ln     <<<BTN * FN / 8, 256>>>(gamma, beta);
    k_selgemm<<<dim3(2, 128), 256>>>(sw1, sb1);
    k_sres   <<<BTN / 8, 256>>>(ssw, ssb);
    k_sel    <<<BTN / 8, 256>>>(sw2, sb2, swg, sbg, swf, sbf, sgm, sbt);
    k_out    <<<BTN / 4, 256>>>(out);
}

// round 2
// speedup vs baseline: 1.0011x; 1.0011x over previous
#include <cuda_runtime.h>
#include <math.h>

#define BTN 16384   // B*T
#define FN  32      // features
#define HN  256     // hidden
#define FHN 8192    // F*H

// Scratch (allocation-free contract: __device__ globals)
__device__ float g_h1 [(size_t)BTN * FN * HN];   // [f][bt][h]  536MB
__device__ float g_stk[(size_t)BTN * FN * HN];   // [bt][f][h]  536MB (pre-LN then LN'd in place)
__device__ float g_sh [(size_t)BTN * HN];        // 16MB
__device__ float g_sres[BTN * FN];               // 2MB
__device__ float g_wts [BTN * FN];               // 2MB

__device__ __forceinline__ float eluf(float z) { return z > 0.f ? z : (expf(z) - 1.f); }
__device__ __forceinline__ float sigf(float z) { return 1.f / (1.f + expf(-z)); }

// ---------------------------------------------------------------------------
// Stage A: per feature f, h1 = ELU(x_f * w1[f] + b1[f]) @ w2[f] + b2[f]
// GEMM 16384 x 256 x 256, A generated on the fly. Tile 128x128x8, 256 thr.
// ---------------------------------------------------------------------------
__global__ __launch_bounds__(256) void k_stageA(
    const float* __restrict__ x,  const float* __restrict__ w1, const float* __restrict__ b1,
    const float* __restrict__ w2, const float* __restrict__ b2)
{
    const int f  = blockIdx.z;
    const int m0 = blockIdx.y * 128;
    const int n0 = blockIdx.x * 128;
    __shared__ float As[8][128];
    __shared__ float Bs[8][128];
    const int tid  = threadIdx.x;
    const int tx   = tid & 15, ty = tid >> 4;
    const int aRow = tid >> 1, aCol = (tid & 1) << 2;
    const int bRow = tid >> 5, bCol = (tid & 31) << 2;
    const float* __restrict__ w2f = w2 + (size_t)f * HN * HN;
    const float xv = x[(m0 + aRow) * FN + f];

    float acc[8][8];
#pragma unroll
    for (int i = 0; i < 8; i++)
#pragma unroll
        for (int j = 0; j < 8; j++) acc[i][j] = 0.f;

    for (int k0 = 0; k0 < HN; k0 += 8) {
        float4 wv = *(const float4*)(w1 + f * HN + k0 + aCol);
        float4 bv = *(const float4*)(b1 + f * HN + k0 + aCol);
        As[aCol + 0][aRow] = eluf(xv * wv.x + bv.x);
        As[aCol + 1][aRow] = eluf(xv * wv.y + bv.y);
        As[aCol + 2][aRow] = eluf(xv * wv.z + bv.z);
        As[aCol + 3][aRow] = eluf(xv * wv.w + bv.w);
        *(float4*)&Bs[bRow][bCol] =
            *(const float4*)(w2f + (size_t)(k0 + bRow) * HN + n0 + bCol);
        __syncthreads();
#pragma unroll
        for (int kk = 0; kk < 8; kk++) {
            float4 a0 = *(const float4*)&As[kk][ty * 4];
            float4 a1 = *(const float4*)&As[kk][64 + ty * 4];
            float4 c0 = *(const float4*)&Bs[kk][tx * 4];
            float4 c1 = *(const float4*)&Bs[kk][64 + tx * 4];
            float ar[8] = {a0.x, a0.y, a0.z, a0.w, a1.x, a1.y, a1.z, a1.w};
            float br[8] = {c0.x, c0.y, c0.z, c0.w, c1.x, c1.y, c1.z, c1.w};
#pragma unroll
            for (int i = 0; i < 8; i++)
#pragma unroll
                for (int j = 0; j < 8; j++) acc[i][j] += ar[i] * br[j];
        }
        __syncthreads();
    }
#pragma unroll
    for (int ih = 0; ih < 2; ih++)
#pragma unroll
        for (int i = 0; i < 4; i++) {
            const int m = m0 + ih * 64 + ty * 4 + i;
            const size_t rb = ((size_t)f * BTN + m) * HN;
#pragma unroll
            for (int jh = 0; jh < 2; jh++) {
                const int n = n0 + jh * 64 + tx * 4;
                float4 b2v = *(const float4*)(b2 + f * HN + n);
                float4 o;
                o.x = acc[ih * 4 + i][jh * 4 + 0] + b2v.x;
                o.y = acc[ih * 4 + i][jh * 4 + 1] + b2v.y;
                o.z = acc[ih * 4 + i][jh * 4 + 2] + b2v.z;
                o.w = acc[ih * 4 + i][jh * 4 + 3] + b2v.w;
                *(float4*)(g_h1 + rb + n) = o;
            }
        }
}

// ---------------------------------------------------------------------------
// Stage B: per feature f, dual GEMM (wg, wf) sharing A = h1_f, fused GLU +
// skip residual. Writes pre-LN values into g_stk[bt][f][h].
// Tile 128x64x8, 256 thr, 8x4 per-thread per GEMM.
// ---------------------------------------------------------------------------
__global__ __launch_bounds__(256) void k_stageB(
    const float* __restrict__ x,
    const float* __restrict__ wg, const float* __restrict__ bg,
    const float* __restrict__ wf, const float* __restrict__ bf,
    const float* __restrict__ ws, const float* __restrict__ bs)
{
    const int f  = blockIdx.z;
    const int m0 = blockIdx.y * 128;
    const int n0 = blockIdx.x * 64;
    __shared__ float As[8][128];
    __shared__ float Bgs[8][64];
    __shared__ float Bvs[8][64];
    const int tid  = threadIdx.x;
    const int tx   = tid & 15, ty = tid >> 4;
    const int aRow = tid >> 1, aCol = (tid & 1) << 2;
    const int bRow = tid >> 5, bCol = (tid & 31) << 1;
    const float* __restrict__ A   = g_h1 + (size_t)f * BTN * HN;
    const float* __restrict__ wgf = wg + (size_t)f * HN * HN;
    const float* __restrict__ wff = wf + (size_t)f * HN * HN;

    float accg[8][4], accv[8][4];
#pragma unroll
    for (int i = 0; i < 8; i++)
#pragma unroll
        for (int j = 0; j < 4; j++) { accg[i][j] = 0.f; accv[i][j] = 0.f; }

    for (int k0 = 0; k0 < HN; k0 += 8) {
        float4 av = *(const float4*)(A + (size_t)(m0 + aRow) * HN + k0 + aCol);
        As[aCol + 0][aRow] = av.x;
        As[aCol + 1][aRow] = av.y;
        As[aCol + 2][aRow] = av.z;
        As[aCol + 3][aRow] = av.w;
        *(float2*)&Bgs[bRow][bCol] =
            *(const float2*)(wgf + (size_t)(k0 + bRow) * HN + n0 + bCol);
        *(float2*)&Bvs[bRow][bCol] =
            *(const float2*)(wff + (size_t)(k0 + bRow) * HN + n0 + bCol);
        __syncthreads();
#pragma unroll
        for (int kk = 0; kk < 8; kk++) {
            float4 a0 = *(const float4*)&As[kk][ty * 4];
            float4 a1 = *(const float4*)&As[kk][64 + ty * 4];
            float4 g4 = *(const float4*)&Bgs[kk][tx * 4];
            float4 v4 = *(const float4*)&Bvs[kk][tx * 4];
            float ar[8]  = {a0.x, a0.y, a0.z, a0.w, a1.x, a1.y, a1.z, a1.w};
            float brg[4] = {g4.x, g4.y, g4.z, g4.w};
            float brv[4] = {v4.x, v4.y, v4.z, v4.w};
#pragma unroll
            for (int i = 0; i < 8; i++)
#pragma unroll
                for (int j = 0; j < 4; j++) {
                    accg[i][j] += ar[i] * brg[j];
                    accv[i][j] += ar[i] * brv[j];
                }
        }
        __syncthreads();
    }
    const int n = n0 + tx * 4;
    float4 bgv = *(const float4*)(bg + f * HN + n);
    float4 bfv = *(const float4*)(bf + f * HN + n);
    float4 wsv = *(const float4*)(ws + f * HN + n);
    float4 bsv = *(const float4*)(bs + f * HN + n);
#pragma unroll
    for (int ih = 0; ih < 2; ih++)
#pragma unroll
        for (int i = 0; i < 4; i++) {
            const int m = m0 + ih * 64 + ty * 4 + i;
            const float xv = x[m * FN + f];
            const int r = ih * 4 + i;
            float4 o;
            o.x = sigf(accg[r][0] + bgv.x) * (accv[r][0] + bfv.x) + xv * wsv.x + bsv.x;
            o.y = sigf(accg[r][1] + bgv.y) * (accv[r][1] + bfv.y) + xv * wsv.y + bsv.y;
            o.z = sigf(accg[r][2] + bgv.z) * (accv[r][2] + bfv.z) + xv * wsv.z + bsv.z;
            o.w = sigf(accg[r][3] + bgv.w) * (accv[r][3] + bfv.w) + xv * wsv.w + bsv.w;
            *(float4*)(g_stk + (size_t)m * FHN + f * HN + n) = o;
        }
}

// ---------------------------------------------------------------------------
// LayerNorm over H=256 per (bt, f) row, in place. One warp per row.
// ---------------------------------------------------------------------------
__global__ __launch_bounds__(256) void k_ln(
    const float* __restrict__ gamma, const float* __restrict__ beta)
{
    const int lane = threadIdx.x & 31;
    const int row  = blockIdx.x * 8 + (threadIdx.x >> 5);   // bt*F + f
    const int f    = row & (FN - 1);
    float* __restrict__ p = g_stk + (size_t)row * HN;
    float v[8];
    float s = 0.f;
#pragma unroll
    for (int i = 0; i < 8; i++) { v[i] = p[i * 32 + lane]; s += v[i]; }
#pragma unroll
    for (int o = 16; o > 0; o >>= 1) s += __shfl_xor_sync(0xffffffffu, s, o);
    const float mean = s * (1.f / 256.f);
    float q = 0.f;
#pragma unroll
    for (int i = 0; i < 8; i++) { float d = v[i] - mean; q += d * d; }
#pragma unroll
    for (int o = 16; o > 0; o >>= 1) q += __shfl_xor_sync(0xffffffffu, q, o);
    const float rstd = rsqrtf(q * (1.f / 256.f) + 1e-5f);
#pragma unroll
    for (int i = 0; i < 8; i++) {
        const int h = i * 32 + lane;
        p[h] = (v[i] - mean) * rstd * gamma[f * HN + h] + beta[f * HN + h];
    }
}

// ---------------------------------------------------------------------------
// Selection GEMM: sh = ELU(flat(16384x8192) @ sw1(8192x256) + sb1)
// Tile 128x128x8.
// ---------------------------------------------------------------------------
__global__ __launch_bounds__(256) void k_selgemm(
    const float* __restrict__ sw1, const float* __restrict__ sb1)
{
    const int m0 = blockIdx.y * 128;
    const int n0 = blockIdx.x * 128;
    __shared__ float As[8][128];
    __shared__ float Bs[8][128];
    const int tid  = threadIdx.x;
    const int tx   = tid & 15, ty = tid >> 4;
    const int aRow = tid >> 1, aCol = (tid & 1) << 2;
    const int bRow = tid >> 5, bCol = (tid & 31) << 2;

    float acc[8][8];
#pragma unroll
    for (int i = 0; i < 8; i++)
#pragma unroll
        for (int j = 0; j < 8; j++) acc[i][j] = 0.f;

    for (int k0 = 0; k0 < FHN; k0 += 8) {
        float4 av = *(const float4*)(g_stk + (size_t)(m0 + aRow) * FHN + k0 + aCol);
        As[aCol + 0][aRow] = av.x;
        As[aCol + 1][aRow] = av.y;
        As[aCol + 2][aRow] = av.z;
        As[aCol + 3][aRow] = av.w;
        *(float4*)&Bs[bRow][bCol] =
            *(const float4*)(sw1 + (size_t)(k0 + bRow) * HN + n0 + bCol);
        __syncthreads();
#pragma unroll
        for (int kk = 0; kk < 8; kk++) {
            float4 a0 = *(const float4*)&As[kk][ty * 4];
            float4 a1 = *(const float4*)&As[kk][64 + ty * 4];
            float4 c0 = *(const float4*)&Bs[kk][tx * 4];
            float4 c1 = *(const float4*)&Bs[kk][64 + tx * 4];
            float ar[8] = {a0.x, a0.y, a0.z, a0.w, a1.x, a1.y, a1.z, a1.w};
            float br[8] = {c0.x, c0.y, c0.z, c0.w, c1.x, c1.y, c1.z, c1.w};
#pragma unroll
            for (int i = 0; i < 8; i++)
#pragma unroll
                for (int j = 0; j < 8; j++) acc[i][j] += ar[i] * br[j];
        }
        __syncthreads();
    }
#pragma unroll
    for (int ih = 0; ih < 2; ih++)
#pragma unroll
        for (int i = 0; i < 4; i++) {
            const int m = m0 + ih * 64 + ty * 4 + i;
#pragma unroll
            for (int jh = 0; jh < 2; jh++) {
                const int n = n0 + jh * 64 + tx * 4;
                float4 bb = *(const float4*)(sb1 + n);
                float4 o;
                o.x = eluf(acc[ih * 4 + i][jh * 4 + 0] + bb.x);
                o.y = eluf(acc[ih * 4 + i][jh * 4 + 1] + bb.y);
                o.z = eluf(acc[ih * 4 + i][jh * 4 + 2] + bb.z);
                o.w = eluf(acc[ih * 4 + i][jh * 4 + 3] + bb.w);
                *(float4*)(g_sh + (size_t)m * HN + n) = o;
            }
        }
}

// ---------------------------------------------------------------------------
// sres = flat @ ssw(8192x32) + ssb. One warp per token, lane = output col.
// ---------------------------------------------------------------------------
__global__ __launch_bounds__(256) void k_sres(
    const float* __restrict__ ssw, const float* __restrict__ ssb)
{
    const int lane = threadIdx.x & 31;
    const int m    = blockIdx.x * 8 + (threadIdx.x >> 5);
    const float* __restrict__ a = g_stk + (size_t)m * FHN;
    float acc = 0.f;
#pragma unroll 4
    for (int k = 0; k < FHN; k += 4) {
        float4 av = *(const float4*)(a + k);
        acc += av.x * ssw[(k + 0) * FN + lane];
        acc += av.y * ssw[(k + 1) * FN + lane];
        acc += av.z * ssw[(k + 2) * FN + lane];
        acc += av.w * ssw[(k + 3) * FN + lane];
    }
    g_sres[m * FN + lane] = acc + ssb[lane];
}

// ---------------------------------------------------------------------------
// Small selection tail: sh2 = sh@sw2+sb2; sglu; + sres; LN(32); softmax.
// One warp per token, lane = feature index.
// ---------------------------------------------------------------------------
__global__ __launch_bounds__(256) void k_sel(
    const float* __restrict__ sw2, const float* __restrict__ sb2,
    const float* __restrict__ swg, const float* __restrict__ sbg,
    const float* __restrict__ swf, const float* __restrict__ sbf,
    const float* __restrict__ sgm, const float* __restrict__ sbt)
{
    const int lane = threadIdx.x & 31;
    const int m    = blockIdx.x * 8 + (threadIdx.x >> 5);
    const float* __restrict__ sh = g_sh + (size_t)m * HN;
    float shv[8];
#pragma unroll
    for (int i = 0; i < 8; i++) shv[i] = sh[i * 32 + lane];
    float acc = sb2[lane];
#pragma unroll 8
    for (int h = 0; h < HN; h++) {
        float s = __shfl_sync(0xffffffffu, shv[h >> 5], h & 31);
        acc += s * sw2[h * FN + lane];
    }
    float ag = sbg[lane], af = sbf[lane];
#pragma unroll
    for (int i = 0; i < FN; i++) {
        float s = __shfl_sync(0xffffffffu, acc, i);
        ag += s * swg[i * FN + lane];
        af += s * swf[i * FN + lane];
    }
    const float pre = g_sres[m * FN + lane] + sigf(ag) * af;
    float s1 = pre;
#pragma unroll
    for (int o = 16; o > 0; o >>= 1) s1 += __shfl_xor_sync(0xffffffffu, s1, o);
    const float mean = s1 * (1.f / 32.f);
    const float d = pre - mean;
    float q = d * d;
#pragma unroll
    for (int o = 16; o > 0; o >>= 1) q += __shfl_xor_sync(0xffffffffu, q, o);
    const float y = d * rsqrtf(q * (1.f / 32.f) + 1e-5f) * sgm[lane] + sbt[lane];
    float mx = y;
#pragma unroll
    for (int o = 16; o > 0; o >>= 1) mx = fmaxf(mx, __shfl_xor_sync(0xffffffffu, mx, o));
    const float e = expf(y - mx);
    float se = e;
#pragma unroll
    for (int o = 16; o > 0; o >>= 1) se += __shfl_xor_sync(0xffffffffu, se, o);
    g_wts[m * FN + lane] = e / se;
}

// ---------------------------------------------------------------------------
// out[bt,h] = sum_f stacked[bt,f,h] * weights[bt,f]. Memory-bound pass.
// ---------------------------------------------------------------------------
__global__ __launch_bounds__(256) void k_out(float* __restrict__ out)
{
    const int m = blockIdx.x * 4 + (threadIdx.x >> 6);
    const int c = threadIdx.x & 63;   // float4 chunk of H
    const float4* __restrict__ sp = (const float4*)(g_stk + (size_t)m * FHN);
    const float* __restrict__ wp = g_wts + m * FN;
    float4 acc = make_float4(0.f, 0.f, 0.f, 0.f);
#pragma unroll
    for (int f = 0; f < FN; f++) {
        const float w = wp[f];
        float4 v = sp[f * 64 + c];
        acc.x += w * v.x; acc.y += w * v.y; acc.z += w * v.z; acc.w += w * v.w;
    }
    ((float4*)out)[(size_t)m * 64 + c] = acc;
}

// ---------------------------------------------------------------------------
extern "C" void kernel_launch(void* const* d_in, const int* in_sizes, int n_in,
                              void* d_out, int out_size)
{
    const float* x    = (const float*)d_in[0];
    const float* w1   = (const float*)d_in[1];
    const float* b1   = (const float*)d_in[2];
    const float* w2   = (const float*)d_in[3];
    const float* b2   = (const float*)d_in[4];
    const float* wg   = (const float*)d_in[5];
    const float* bg   = (const float*)d_in[6];
    const float* wf   = (const float*)d_in[7];
    const float* bf   = (const float*)d_in[8];
    const float* gamma= (const float*)d_in[9];
    const float* beta = (const float*)d_in[10];
    const float* ws   = (const float*)d_in[11];
    const float* bs   = (const float*)d_in[12];
    const float* sw1  = (const float*)d_in[13];
    const float* sb1  = (const float*)d_in[14];
    const float* sw2  = (const float*)d_in[15];
    const float* sb2  = (const float*)d_in[16];
    const float* swg  = (const float*)d_in[17];
    const float* sbg  = (const float*)d_in[18];
    const float* swf  = (const float*)d_in[19];
    const float* sbf  = (const float*)d_in[20];
    const float* sgm  = (const float*)d_in[21];
    const float* sbt  = (const float*)d_in[22];
    const float* ssw  = (const float*)d_in[23];
    const float* ssb  = (const float*)d_in[24];
    float* out = (float*)d_out;

    k_stageA <<<dim3(2, 128, 32), 256>>>(x, w1, b1, w2, b2);
    k_stageB <<<dim3(4, 128, 32), 256>>>(x, wg, bg, wf, bf, ws, bs);
    k_ln     <<<BTN * FN / 8, 256>>>(gamma, beta);
    k_selgemm<<<dim3(2, 128), 256>>>(sw1, sb1);
    k_sres   <<<BTN / 8, 256>>>(ssw, ssb);
    k_sel    <<<BTN / 8, 256>>>(sw2, sb2, swg, sbg, swf, sbf, sgm, sbt);
    k_out    <<<BTN / 4, 256>>>(out);
}

// round 5
// speedup vs baseline: 1.3365x; 1.3350x over previous
#include <cuda_runtime.h>
#include <cuda_bf16.h>
#include <math.h>
#include <stdint.h>

#define BTN 16384
#define FN  32
#define HN  256
#define FHN 8192

// ---------------- scratch ----------------
__device__ float g_h1 [(size_t)BTN * FN * HN];   // [f][bt][h]
__device__ float g_stk[(size_t)BTN * FN * HN];   // [bt][f*H+h]
__device__ float g_sh [(size_t)BTN * HN];
__device__ float g_sres[BTN * FN];
__device__ float g_wts [BTN * FN];

__device__ __forceinline__ float eluf(float z) { return z > 0.f ? z : (__expf(z) - 1.f); }
__device__ __forceinline__ float sigf(float z) { return 1.f / (1.f + __expf(-z)); }

__device__ __forceinline__ uint32_t smem_u32(const void* p) {
    uint32_t a;
    asm("{ .reg .u64 t; cvta.to.shared.u64 t, %1; cvt.u32.u64 %0, t; }" : "=r"(a) : "l"(p));
    return a;
}
__device__ __forceinline__ void ldsm_x4(uint32_t* r, uint32_t a) {
    asm volatile("ldmatrix.sync.aligned.m8n8.x4.shared.b16 {%0,%1,%2,%3}, [%4];"
                 : "=r"(r[0]), "=r"(r[1]), "=r"(r[2]), "=r"(r[3]) : "r"(a));
}
__device__ __forceinline__ void ldsm_x4t(uint32_t* r, uint32_t a) {
    asm volatile("ldmatrix.sync.aligned.m8n8.x4.trans.shared.b16 {%0,%1,%2,%3}, [%4];"
                 : "=r"(r[0]), "=r"(r[1]), "=r"(r[2]), "=r"(r[3]) : "r"(a));
}
__device__ __forceinline__ void mmab(float* d, const uint32_t* a, uint32_t b0, uint32_t b1) {
    asm volatile("mma.sync.aligned.m16n8k16.row.col.f32.bf16.bf16.f32 "
                 "{%0,%1,%2,%3}, {%4,%5,%6,%7}, {%8,%9}, {%0,%1,%2,%3};"
                 : "+f"(d[0]), "+f"(d[1]), "+f"(d[2]), "+f"(d[3])
                 : "r"(a[0]), "r"(a[1]), "r"(a[2]), "r"(a[3]), "r"(b0), "r"(b1));
}
__device__ __forceinline__ uint32_t pack_hi2(float v0, float v1) {
    __nv_bfloat162 p = __floats2bfloat162_rn(v0, v1);
    return *(uint32_t*)&p;
}
__device__ __forceinline__ uint32_t pack_lo2(float v0, float v1) {
    float r0 = v0 - __bfloat162float(__float2bfloat16_rn(v0));
    float r1 = v1 - __bfloat162float(__float2bfloat16_rn(v1));
    __nv_bfloat162 p = __floats2bfloat162_rn(r0, r1);
    return *(uint32_t*)&p;
}

// smem strides (bytes): A rows 32 bf16 -> 80B; B rows 256 bf16 -> 528B
#define AST 80u
#define BST 528u
// layout: Ah 0 | Al 10240 | Bh 20480 | Bl 37376 | end 54272
#define S_AL  10240
#define S_BH  20480
#define S_BL  37376
#define SM_S  54272

// one 32-wide k-chunk: C += (Ah+Al) @ (Bh+Bl) [3-term], M=128 (4 x m16), N=256
__device__ __forceinline__ void ktile1(
    uint32_t aH, uint32_t aL, uint32_t bH, uint32_t bL,
    float (&acc)[4][8][4], int lane, int wm, int wn)
{
#pragma unroll
    for (int k16 = 0; k16 < 32; k16 += 16) {
        uint32_t Ah[4][4], Al[4][4];
#pragma unroll
        for (int mt = 0; mt < 4; mt++) {
            uint32_t ro = (uint32_t)(wm * 64 + mt * 16 + (lane & 15)) * AST
                        + (uint32_t)(k16 + ((lane >> 4) << 3)) * 2u;
            ldsm_x4(Ah[mt], aH + ro);
            ldsm_x4(Al[mt], aL + ro);
        }
        const int mat = lane >> 3;
#pragma unroll
        for (int nq = 0; nq < 4; nq++) {
            const int nb = wn * 64 + nq * 16;
            uint32_t bo = (uint32_t)(k16 + (mat & 1) * 8 + (lane & 7)) * BST
                        + (uint32_t)(nb + (mat >> 1) * 8) * 2u;
            uint32_t bh[4], bl[4];
            ldsm_x4t(bh, bH + bo);
            ldsm_x4t(bl, bL + bo);
#pragma unroll
            for (int mt = 0; mt < 4; mt++) {
                mmab(acc[mt][nq*2+0], Ah[mt], bh[0], bh[1]);
                mmab(acc[mt][nq*2+1], Ah[mt], bh[2], bh[3]);
                mmab(acc[mt][nq*2+0], Al[mt], bh[0], bh[1]);
                mmab(acc[mt][nq*2+1], Al[mt], bh[2], bh[3]);
                mmab(acc[mt][nq*2+0], Ah[mt], bl[0], bl[1]);
                mmab(acc[mt][nq*2+1], Ah[mt], bl[2], bl[3]);
            }
        }
    }
}

// ---------------------------------------------------------------------------
// k_hA (HMMA): h1[f] = ELU(x_f*w1+b1) @ w2[f] + b2.  M=128, N=256, K=256.
// ---------------------------------------------------------------------------
__global__ void __launch_bounds__(256, 1) k_hA(
    const float* __restrict__ x, const float* __restrict__ w1, const float* __restrict__ b1,
    const float* __restrict__ w2, const float* __restrict__ b2)
{
    extern __shared__ char sm[];
    const uint32_t smb = smem_u32(sm);
    const int tid = threadIdx.x, lane = tid & 31, wid = tid >> 5;
    const int wm = wid & 1, wn = wid >> 1;
    const int m0 = blockIdx.x * 128, f = blockIdx.y;

    float acc[4][8][4];
#pragma unroll
    for (int a = 0; a < 4; a++)
#pragma unroll
        for (int b = 0; b < 8; b++)
#pragma unroll
            for (int c = 0; c < 4; c++) acc[a][b][c] = 0.f;

    const int grow = tid & 127, gseg = tid >> 7;   // row, k-half (16 each)
    const float xv = x[(m0 + grow) * FN + f];
    const float* __restrict__ w1f = w1 + f * HN;
    const float* __restrict__ b1f = b1 + f * HN;

    for (int kt = 0; kt < 8; kt++) {
        const int k0 = kt * 32;
        // generate + split A: 128 rows x 32 k
#pragma unroll
        for (int oct = 0; oct < 2; oct++) {
            const int kk = k0 + gseg * 16 + oct * 8;
            float4 wa = *(const float4*)(w1f + kk),  wb = *(const float4*)(w1f + kk + 4);
            float4 ca = *(const float4*)(b1f + kk),  cb = *(const float4*)(b1f + kk + 4);
            float v[8] = { eluf(xv*wa.x+ca.x), eluf(xv*wa.y+ca.y), eluf(xv*wa.z+ca.z), eluf(xv*wa.w+ca.w),
                           eluf(xv*wb.x+cb.x), eluf(xv*wb.y+cb.y), eluf(xv*wb.z+cb.z), eluf(xv*wb.w+cb.w) };
            uint4 H = { pack_hi2(v[0],v[1]), pack_hi2(v[2],v[3]), pack_hi2(v[4],v[5]), pack_hi2(v[6],v[7]) };
            uint4 L = { pack_lo2(v[0],v[1]), pack_lo2(v[2],v[3]), pack_lo2(v[4],v[5]), pack_lo2(v[6],v[7]) };
            const uint32_t o = grow * AST + gseg * 32 + oct * 16;
            *(uint4*)(sm + o) = H;
            *(uint4*)(sm + S_AL + o) = L;
        }
        // load + split B = w2[f][k0..k0+31][0..255]
#pragma unroll
        for (int i = 0; i < 8; i++) {
            const int u = tid + 256 * i;           // 0..2047
            const int row = u >> 6, cu = u & 63;
            float4 v = *(const float4*)(w2 + ((size_t)f * HN + k0 + row) * HN + cu * 4);
            const uint32_t o = row * BST + cu * 8;
            *(uint2*)(sm + S_BH + o) = make_uint2(pack_hi2(v.x, v.y), pack_hi2(v.z, v.w));
            *(uint2*)(sm + S_BL + o) = make_uint2(pack_lo2(v.x, v.y), pack_lo2(v.z, v.w));
        }
        __syncthreads();
        ktile1(smb, smb + S_AL, smb + S_BH, smb + S_BL, acc, lane, wm, wn);
        __syncthreads();
    }
    // epilogue: + b2, store fp32 g_h1[f][m][n]
#pragma unroll
    for (int mt = 0; mt < 4; mt++)
#pragma unroll
        for (int j = 0; j < 8; j++) {
            const int n  = wn * 64 + j * 8 + (lane & 3) * 2;
            const int r0 = wm * 64 + mt * 16 + (lane >> 2);
            float2 bb = *(const float2*)(b2 + f * HN + n);
            float2 o0 = { acc[mt][j][0] + bb.x, acc[mt][j][1] + bb.y };
            float2 o1 = { acc[mt][j][2] + bb.x, acc[mt][j][3] + bb.y };
            *(float2*)(g_h1 + ((size_t)f * BTN + m0 + r0) * HN + n) = o0;
            *(float2*)(g_h1 + ((size_t)f * BTN + m0 + r0 + 8) * HN + n) = o1;
        }
}

// ---------------------------------------------------------------------------
// k_hS (HMMA): sh = ELU(g_stk(16384x8192) @ sw1 + sb1). M=128, N=256, K=8192.
// ---------------------------------------------------------------------------
__global__ void __launch_bounds__(256, 1) k_hS(
    const float* __restrict__ sw1, const float* __restrict__ sb1)
{
    extern __shared__ char sm[];
    const uint32_t smb = smem_u32(sm);
    const int tid = threadIdx.x, lane = tid & 31, wid = tid >> 5;
    const int wm = wid & 1, wn = wid >> 1;
    const int m0 = blockIdx.x * 128;

    float acc[4][8][4];
#pragma unroll
    for (int a = 0; a < 4; a++)
#pragma unroll
        for (int b = 0; b < 8; b++)
#pragma unroll
            for (int c = 0; c < 4; c++) acc[a][b][c] = 0.f;

    for (int kt = 0; kt < FHN / 32; kt++) {
        const int k0 = kt * 32;
        // A: 128 rows x 32 fp32 -> split
#pragma unroll
        for (int i = 0; i < 4; i++) {
            const int u = tid + 256 * i;          // 0..1023
            const int row = u >> 3, cu = u & 7;
            float4 v = *(const float4*)(g_stk + (size_t)(m0 + row) * FHN + k0 + cu * 4);
            const uint32_t o = row * AST + cu * 8;
            *(uint2*)(sm + o)        = make_uint2(pack_hi2(v.x, v.y), pack_hi2(v.z, v.w));
            *(uint2*)(sm + S_AL + o) = make_uint2(pack_lo2(v.x, v.y), pack_lo2(v.z, v.w));
        }
        // B: 32 rows x 256 fp32 -> split
#pragma unroll
        for (int i = 0; i < 8; i++) {
            const int u = tid + 256 * i;          // 0..2047
            const int row = u >> 6, cu = u & 63;
            float4 v = *(const float4*)(sw1 + (size_t)(k0 + row) * HN + cu * 4);
            const uint32_t o = row * BST + cu * 8;
            *(uint2*)(sm + S_BH + o) = make_uint2(pack_hi2(v.x, v.y), pack_hi2(v.z, v.w));
            *(uint2*)(sm + S_BL + o) = make_uint2(pack_lo2(v.x, v.y), pack_lo2(v.z, v.w));
        }
        __syncthreads();
        ktile1(smb, smb + S_AL, smb + S_BH, smb + S_BL, acc, lane, wm, wn);
        __syncthreads();
    }
    // epilogue: + sb1, ELU, store fp32
#pragma unroll
    for (int mt = 0; mt < 4; mt++)
#pragma unroll
        for (int j = 0; j < 8; j++) {
            const int n  = wn * 64 + j * 8 + (lane & 3) * 2;
            const int r0 = wm * 64 + mt * 16 + (lane >> 2);
            float2 bb = *(const float2*)(sb1 + n);
            float2 o0 = { eluf(acc[mt][j][0] + bb.x), eluf(acc[mt][j][1] + bb.y) };
            float2 o1 = { eluf(acc[mt][j][2] + bb.x), eluf(acc[mt][j][3] + bb.y) };
            *(float2*)(g_sh + (size_t)(m0 + r0) * HN + n) = o0;
            *(float2*)(g_sh + (size_t)(m0 + r0 + 8) * HN + n) = o1;
        }
}

// ---------------------------------------------------------------------------
// Stage B (fp32, proven): dual GEMM (wg, wf) on A = h1_f, GLU + skip fused.
// ---------------------------------------------------------------------------
__global__ __launch_bounds__(256) void k_stageB(
    const float* __restrict__ x,
    const float* __restrict__ wg, const float* __restrict__ bg,
    const float* __restrict__ wf, const float* __restrict__ bf,
    const float* __restrict__ ws, const float* __restrict__ bs)
{
    const int f  = blockIdx.z;
    const int m0 = blockIdx.y * 128;
    const int n0 = blockIdx.x * 64;
    __shared__ float As[8][128];
    __shared__ float Bgs[8][64];
    __shared__ float Bvs[8][64];
    const int tid  = threadIdx.x;
    const int tx   = tid & 15, ty = tid >> 4;
    const int aRow = tid >> 1, aCol = (tid & 1) << 2;
    const int bRow = tid >> 5, bCol = (tid & 31) << 1;
    const float* __restrict__ A   = g_h1 + (size_t)f * BTN * HN;
    const float* __restrict__ wgf = wg + (size_t)f * HN * HN;
    const float* __restrict__ wff = wf + (size_t)f * HN * HN;

    float accg[8][4], accv[8][4];
#pragma unroll
    for (int i = 0; i < 8; i++)
#pragma unroll
        for (int j = 0; j < 4; j++) { accg[i][j] = 0.f; accv[i][j] = 0.f; }

    for (int k0 = 0; k0 < HN; k0 += 8) {
        float4 av = *(const float4*)(A + (size_t)(m0 + aRow) * HN + k0 + aCol);
        As[aCol + 0][aRow] = av.x;
        As[aCol + 1][aRow] = av.y;
        As[aCol + 2][aRow] = av.z;
        As[aCol + 3][aRow] = av.w;
        *(float2*)&Bgs[bRow][bCol] =
            *(const float2*)(wgf + (size_t)(k0 + bRow) * HN + n0 + bCol);
        *(float2*)&Bvs[bRow][bCol] =
            *(const float2*)(wff + (size_t)(k0 + bRow) * HN + n0 + bCol);
        __syncthreads();
#pragma unroll
        for (int kk = 0; kk < 8; kk++) {
            float4 a0 = *(const float4*)&As[kk][ty * 4];
            float4 a1 = *(const float4*)&As[kk][64 + ty * 4];
            float4 g4 = *(const float4*)&Bgs[kk][tx * 4];
            float4 v4 = *(const float4*)&Bvs[kk][tx * 4];
            float ar[8]  = {a0.x, a0.y, a0.z, a0.w, a1.x, a1.y, a1.z, a1.w};
            float brg[4] = {g4.x, g4.y, g4.z, g4.w};
            float brv[4] = {v4.x, v4.y, v4.z, v4.w};
#pragma unroll
            for (int i = 0; i < 8; i++)
#pragma unroll
                for (int j = 0; j < 4; j++) {
                    accg[i][j] += ar[i] * brg[j];
                    accv[i][j] += ar[i] * brv[j];
                }
        }
        __syncthreads();
    }
    const int n = n0 + tx * 4;
    float4 bgv = *(const float4*)(bg + f * HN + n);
    float4 bfv = *(const float4*)(bf + f * HN + n);
    float4 wsv = *(const float4*)(ws + f * HN + n);
    float4 bsv = *(const float4*)(bs + f * HN + n);
#pragma unroll
    for (int ih = 0; ih < 2; ih++)
#pragma unroll
        for (int i = 0; i < 4; i++) {
            const int m = m0 + ih * 64 + ty * 4 + i;
            const float xv = x[m * FN + f];
            const int r = ih * 4 + i;
            float4 o;
            o.x = sigf(accg[r][0] + bgv.x) * (accv[r][0] + bfv.x) + xv * wsv.x + bsv.x;
            o.y = sigf(accg[r][1] + bgv.y) * (accv[r][1] + bfv.y) + xv * wsv.y + bsv.y;
            o.z = sigf(accg[r][2] + bgv.z) * (accv[r][2] + bfv.z) + xv * wsv.z + bsv.z;
            o.w = sigf(accg[r][3] + bgv.w) * (accv[r][3] + bfv.w) + xv * wsv.w + bsv.w;
            *(float4*)(g_stk + (size_t)m * FHN + f * HN + n) = o;
        }
}

// ---------------------------------------------------------------------------
__global__ __launch_bounds__(256) void k_ln(
    const float* __restrict__ gamma, const float* __restrict__ beta)
{
    const int lane = threadIdx.x & 31;
    const int row  = blockIdx.x * 8 + (threadIdx.x >> 5);
    const int f    = row & (FN - 1);
    float* __restrict__ p = g_stk + (size_t)row * HN;
    float v[8];
    float s = 0.f;
#pragma unroll
    for (int i = 0; i < 8; i++) { v[i] = p[i * 32 + lane]; s += v[i]; }
#pragma unroll
    for (int o = 16; o > 0; o >>= 1) s += __shfl_xor_sync(0xffffffffu, s, o);
    const float mean = s * (1.f / 256.f);
    float q = 0.f;
#pragma unroll
    for (int i = 0; i < 8; i++) { float d = v[i] - mean; q += d * d; }
#pragma unroll
    for (int o = 16; o > 0; o >>= 1) q += __shfl_xor_sync(0xffffffffu, q, o);
    const float rstd = rsqrtf(q * (1.f / 256.f) + 1e-5f);
#pragma unroll
    for (int i = 0; i < 8; i++) {
        const int h = i * 32 + lane;
        p[h] = (v[i] - mean) * rstd * gamma[f * HN + h] + beta[f * HN + h];
    }
}

// ---------------------------------------------------------------------------
__global__ __launch_bounds__(256) void k_sres(
    const float* __restrict__ ssw, const float* __restrict__ ssb)
{
    const int lane = threadIdx.x & 31;
    const int m    = blockIdx.x * 8 + (threadIdx.x >> 5);
    const float* __restrict__ a = g_stk + (size_t)m * FHN;
    float acc = 0.f;
#pragma unroll 4
    for (int k = 0; k < FHN; k += 4) {
        float4 av = *(const float4*)(a + k);
        acc += av.x * ssw[(k + 0) * FN + lane];
        acc += av.y * ssw[(k + 1) * FN + lane];
        acc += av.z * ssw[(k + 2) * FN + lane];
        acc += av.w * ssw[(k + 3) * FN + lane];
    }
    g_sres[m * FN + lane] = acc + ssb[lane];
}

// ---------------------------------------------------------------------------
__global__ __launch_bounds__(256) void k_sel(
    const float* __restrict__ sw2, const float* __restrict__ sb2,
    const float* __restrict__ swg, const float* __restrict__ sbg,
    const float* __restrict__ swf, const float* __restrict__ sbf,
    const float* __restrict__ sgm, const float* __restrict__ sbt)
{
    const int lane = threadIdx.x & 31;
    const int m    = blockIdx.x * 8 + (threadIdx.x >> 5);
    const float* __restrict__ sh = g_sh + (size_t)m * HN;
    float shv[8];
#pragma unroll
    for (int i = 0; i < 8; i++) shv[i] = sh[i * 32 + lane];
    float acc = sb2[lane];
#pragma unroll 8
    for (int h = 0; h < HN; h++) {
        float s = __shfl_sync(0xffffffffu, shv[h >> 5], h & 31);
        acc += s * sw2[h * FN + lane];
    }
    float ag = sbg[lane], af = sbf[lane];
#pragma unroll
    for (int i = 0; i < FN; i++) {
        float s = __shfl_sync(0xffffffffu, acc, i);
        ag += s * swg[i * FN + lane];
        af += s * swf[i * FN + lane];
    }
    const float pre = g_sres[m * FN + lane] + sigf(ag) * af;
    float s1 = pre;
#pragma unroll
    for (int o = 16; o > 0; o >>= 1) s1 += __shfl_xor_sync(0xffffffffu, s1, o);
    const float mean = s1 * (1.f / 32.f);
    const float d = pre - mean;
    float q = d * d;
#pragma unroll
    for (int o = 16; o > 0; o >>= 1) q += __shfl_xor_sync(0xffffffffu, q, o);
    const float y = d * rsqrtf(q * (1.f / 32.f) + 1e-5f) * sgm[lane] + sbt[lane];
    float mx = y;
#pragma unroll
    for (int o = 16; o > 0; o >>= 1) mx = fmaxf(mx, __shfl_xor_sync(0xffffffffu, mx, o));
    const float e = __expf(y - mx);
    float se = e;
#pragma unroll
    for (int o = 16; o > 0; o >>= 1) se += __shfl_xor_sync(0xffffffffu, se, o);
    g_wts[m * FN + lane] = e / se;
}

// ---------------------------------------------------------------------------
__global__ __launch_bounds__(256) void k_out(float* __restrict__ out)
{
    const int m = blockIdx.x * 4 + (threadIdx.x >> 6);
    const int c = threadIdx.x & 63;
    const float4* __restrict__ sp = (const float4*)(g_stk + (size_t)m * FHN);
    const float* __restrict__ wp = g_wts + m * FN;
    float4 acc = make_float4(0.f, 0.f, 0.f, 0.f);
#pragma unroll
    for (int f = 0; f < FN; f++) {
        const float w = wp[f];
        float4 v = sp[f * 64 + c];
        acc.x += w * v.x; acc.y += w * v.y; acc.z += w * v.z; acc.w += w * v.w;
    }
    ((float4*)out)[(size_t)m * 64 + c] = acc;
}

// ---------------------------------------------------------------------------
extern "C" void kernel_launch(void* const* d_in, const int* in_sizes, int n_in,
                              void* d_out, int out_size)
{
    const float* x    = (const float*)d_in[0];
    const float* w1   = (const float*)d_in[1];
    const float* b1   = (const float*)d_in[2];
    const float* w2   = (const float*)d_in[3];
    const float* b2   = (const float*)d_in[4];
    const float* wg   = (const float*)d_in[5];
    const float* bg   = (const float*)d_in[6];
    const float* wf   = (const float*)d_in[7];
    const float* bf   = (const float*)d_in[8];
    const float* gamma= (const float*)d_in[9];
    const float* beta = (const float*)d_in[10];
    const float* ws   = (const float*)d_in[11];
    const float* bs   = (const float*)d_in[12];
    const float* sw1  = (const float*)d_in[13];
    const float* sb1  = (const float*)d_in[14];
    const float* sw2  = (const float*)d_in[15];
    const float* sb2  = (const float*)d_in[16];
    const float* swg  = (const float*)d_in[17];
    const float* sbg  = (const float*)d_in[18];
    const float* swf  = (const float*)d_in[19];
    const float* sbf  = (const float*)d_in[20];
    const float* sgm  = (const float*)d_in[21];
    const float* sbt  = (const float*)d_in[22];
    const float* ssw  = (const float*)d_in[23];
    const float* ssb  = (const float*)d_in[24];
    float* out = (float*)d_out;

    cudaFuncSetAttribute(k_hA, cudaFuncAttributeMaxDynamicSharedMemorySize, SM_S);
    cudaFuncSetAttribute(k_hS, cudaFuncAttributeMaxDynamicSharedMemorySize, SM_S);

    k_hA    <<<dim3(BTN / 128, FN), 256, SM_S>>>(x, w1, b1, w2, b2);
    k_stageB<<<dim3(4, 128, 32), 256>>>(x, wg, bg, wf, bf, ws, bs);
    k_ln    <<<BTN * FN / 8, 256>>>(gamma, beta);
    k_hS    <<<BTN / 128, 256, SM_S>>>(sw1, sb1);
    k_sres  <<<BTN / 8, 256>>>(ssw, ssb);
    k_sel   <<<BTN / 8, 256>>>(sw2, sb2, swg, sbg, swf, sbf, sgm, sbt);
    k_out   <<<BTN / 4, 256>>>(out);
}

// round 6
// speedup vs baseline: 1.7848x; 1.3354x over previous
#include <cuda_runtime.h>
#include <cuda_bf16.h>
#include <math.h>
#include <stdint.h>

#define BTN 16384
#define FN  32
#define HN  256
#define FHN 8192

// ---------------- scratch ----------------
__device__ float g_h1 [(size_t)BTN * FN * HN];   // [f][bt][h]
__device__ float g_pg [(size_t)BTN * FN * HN];   // gate pre-act [f][bt][h]
__device__ float g_pf [(size_t)BTN * FN * HN];   // value pre-act [f][bt][h]
__device__ float g_stk[(size_t)BTN * FN * HN];   // [bt][f*H+h]
__device__ float g_sh [(size_t)BTN * HN];
__device__ float g_sres[BTN * FN];
__device__ float g_wts [BTN * FN];

__device__ __forceinline__ float eluf(float z) { return z > 0.f ? z : (__expf(z) - 1.f); }
__device__ __forceinline__ float sigf(float z) { return 1.f / (1.f + __expf(-z)); }

__device__ __forceinline__ uint32_t smem_u32(const void* p) {
    uint32_t a;
    asm("{ .reg .u64 t; cvta.to.shared.u64 t, %1; cvt.u32.u64 %0, t; }" : "=r"(a) : "l"(p));
    return a;
}
__device__ __forceinline__ void ldsm_x4(uint32_t* r, uint32_t a) {
    asm volatile("ldmatrix.sync.aligned.m8n8.x4.shared.b16 {%0,%1,%2,%3}, [%4];"
                 : "=r"(r[0]), "=r"(r[1]), "=r"(r[2]), "=r"(r[3]) : "r"(a));
}
__device__ __forceinline__ void ldsm_x4t(uint32_t* r, uint32_t a) {
    asm volatile("ldmatrix.sync.aligned.m8n8.x4.trans.shared.b16 {%0,%1,%2,%3}, [%4];"
                 : "=r"(r[0]), "=r"(r[1]), "=r"(r[2]), "=r"(r[3]) : "r"(a));
}
__device__ __forceinline__ void mmab(float* d, const uint32_t* a, uint32_t b0, uint32_t b1) {
    asm volatile("mma.sync.aligned.m16n8k16.row.col.f32.bf16.bf16.f32 "
                 "{%0,%1,%2,%3}, {%4,%5,%6,%7}, {%8,%9}, {%0,%1,%2,%3};"
                 : "+f"(d[0]), "+f"(d[1]), "+f"(d[2]), "+f"(d[3])
                 : "r"(a[0]), "r"(a[1]), "r"(a[2]), "r"(a[3]), "r"(b0), "r"(b1));
}
__device__ __forceinline__ uint32_t pack_hi2(float v0, float v1) {
    __nv_bfloat162 p = __floats2bfloat162_rn(v0, v1);
    return *(uint32_t*)&p;
}
__device__ __forceinline__ uint32_t pack_lo2(float v0, float v1) {
    float r0 = v0 - __bfloat162float(__float2bfloat16_rn(v0));
    float r1 = v1 - __bfloat162float(__float2bfloat16_rn(v1));
    __nv_bfloat162 p = __floats2bfloat162_rn(r0, r1);
    return *(uint32_t*)&p;
}

// smem strides (bytes): A rows 32 bf16 -> 80B; B rows 256 bf16 -> 528B
#define AST 80u
#define BST 528u
// layout: Ah 0 | Al 10240 | Bh 20480 | Bl 37376 | end 54272
#define S_AL  10240
#define S_BH  20480
#define S_BL  37376
#define SM_S  54272

// one 32-wide k-chunk: C += (Ah+Al) @ (Bh+Bl) [3-term], M=128 (4 x m16), N=256
__device__ __forceinline__ void ktile1(
    uint32_t aH, uint32_t aL, uint32_t bH, uint32_t bL,
    float (&acc)[4][8][4], int lane, int wm, int wn)
{
#pragma unroll
    for (int k16 = 0; k16 < 32; k16 += 16) {
        uint32_t Ah[4][4], Al[4][4];
#pragma unroll
        for (int mt = 0; mt < 4; mt++) {
            uint32_t ro = (uint32_t)(wm * 64 + mt * 16 + (lane & 15)) * AST
                        + (uint32_t)(k16 + ((lane >> 4) << 3)) * 2u;
            ldsm_x4(Ah[mt], aH + ro);
            ldsm_x4(Al[mt], aL + ro);
        }
        const int mat = lane >> 3;
#pragma unroll
        for (int nq = 0; nq < 4; nq++) {
            const int nb = wn * 64 + nq * 16;
            uint32_t bo = (uint32_t)(k16 + (mat & 1) * 8 + (lane & 7)) * BST
                        + (uint32_t)(nb + (mat >> 1) * 8) * 2u;
            uint32_t bh[4], bl[4];
            ldsm_x4t(bh, bH + bo);
            ldsm_x4t(bl, bL + bo);
#pragma unroll
            for (int mt = 0; mt < 4; mt++) {
                mmab(acc[mt][nq*2+0], Ah[mt], bh[0], bh[1]);
                mmab(acc[mt][nq*2+1], Ah[mt], bh[2], bh[3]);
                mmab(acc[mt][nq*2+0], Al[mt], bh[0], bh[1]);
                mmab(acc[mt][nq*2+1], Al[mt], bh[2], bh[3]);
                mmab(acc[mt][nq*2+0], Ah[mt], bl[0], bl[1]);
                mmab(acc[mt][nq*2+1], Ah[mt], bl[2], bl[3]);
            }
        }
    }
}

// ---------------------------------------------------------------------------
// Generic HMMA GEMM: C[f] = doElu ? elu(A[f]@B[f] + bias) : A[f]@B[f]
// A fp32 (m0..m0+127 rows, lda), B fp32 (K x 256, row stride HN).
// Register-prefetch pipeline: next tile's LDGs overlap current tile's MMA.
// ---------------------------------------------------------------------------
__global__ void __launch_bounds__(256, 1) k_hmma(
    const float* __restrict__ A, size_t aF, int lda,
    const float* __restrict__ B, size_t bF,
    const float* __restrict__ bias, float* __restrict__ C, size_t cF, int ldc,
    int kTiles, int doElu)
{
    extern __shared__ char sm[];
    const uint32_t smb = smem_u32(sm);
    const int tid = threadIdx.x, lane = tid & 31, wid = tid >> 5;
    const int wm = wid & 1, wn = wid >> 1;
    const int m0 = blockIdx.x * 128, f = blockIdx.y;
    A += aF * f; B += bF * f; C += cF * f;

    float acc[4][8][4];
#pragma unroll
    for (int a = 0; a < 4; a++)
#pragma unroll
        for (int b = 0; b < 8; b++)
#pragma unroll
            for (int c = 0; c < 4; c++) acc[a][b][c] = 0.f;

    float4 ra[4], rb[8];
    const int arow = 0; (void)arow;

#define LOAD_A(kt) do { \
    _Pragma("unroll") \
    for (int i = 0; i < 4; i++) { \
        const int u = tid + 256 * i; \
        const int row = u >> 3, cu = u & 7; \
        ra[i] = *(const float4*)(A + (size_t)(m0 + row) * lda + (kt) * 32 + cu * 4); \
    } } while (0)
#define LOAD_B(kt) do { \
    _Pragma("unroll") \
    for (int i = 0; i < 8; i++) { \
        const int u = tid + 256 * i; \
        const int row = u >> 6, cu = u & 63; \
        rb[i] = *(const float4*)(B + (size_t)((kt) * 32 + row) * HN + cu * 4); \
    } } while (0)

    LOAD_A(0); LOAD_B(0);
    for (int kt = 0; kt < kTiles; kt++) {
        // stage regs -> smem (split bf16 hi/lo)
#pragma unroll
        for (int i = 0; i < 4; i++) {
            const int u = tid + 256 * i;
            const int row = u >> 3, cu = u & 7;
            const uint32_t o = row * AST + cu * 8;
            *(uint2*)(sm + o)        = make_uint2(pack_hi2(ra[i].x, ra[i].y), pack_hi2(ra[i].z, ra[i].w));
            *(uint2*)(sm + S_AL + o) = make_uint2(pack_lo2(ra[i].x, ra[i].y), pack_lo2(ra[i].z, ra[i].w));
        }
#pragma unroll
        for (int i = 0; i < 8; i++) {
            const int u = tid + 256 * i;
            const int row = u >> 6, cu = u & 63;
            const uint32_t o = row * BST + cu * 8;
            *(uint2*)(sm + S_BH + o) = make_uint2(pack_hi2(rb[i].x, rb[i].y), pack_hi2(rb[i].z, rb[i].w));
            *(uint2*)(sm + S_BL + o) = make_uint2(pack_lo2(rb[i].x, rb[i].y), pack_lo2(rb[i].z, rb[i].w));
        }
        __syncthreads();
        if (kt + 1 < kTiles) { LOAD_A(kt + 1); LOAD_B(kt + 1); }
        ktile1(smb, smb + S_AL, smb + S_BH, smb + S_BL, acc, lane, wm, wn);
        __syncthreads();
    }
#undef LOAD_A
#undef LOAD_B

    // epilogue
#pragma unroll
    for (int mt = 0; mt < 4; mt++)
#pragma unroll
        for (int j = 0; j < 8; j++) {
            const int n  = wn * 64 + j * 8 + (lane & 3) * 2;
            const int r0 = wm * 64 + mt * 16 + (lane >> 2);
            float2 bb = bias ? *(const float2*)(bias + n) : make_float2(0.f, 0.f);
            float v0 = acc[mt][j][0] + bb.x, v1 = acc[mt][j][1] + bb.y;
            float v2 = acc[mt][j][2] + bb.x, v3 = acc[mt][j][3] + bb.y;
            if (doElu) { v0 = eluf(v0); v1 = eluf(v1); v2 = eluf(v2); v3 = eluf(v3); }
            *(float2*)(C + (size_t)(m0 + r0) * ldc + n)     = make_float2(v0, v1);
            *(float2*)(C + (size_t)(m0 + r0 + 8) * ldc + n) = make_float2(v2, v3);
        }
}

// ---------------------------------------------------------------------------
// k_hA (HMMA): h1[f] = ELU(x_f*w1+b1) @ w2[f] + b2.  M=128, N=256, K=256.
// B (w2) register-prefetched; A generated on the fly.
// ---------------------------------------------------------------------------
__global__ void __launch_bounds__(256, 1) k_hA(
    const float* __restrict__ x, const float* __restrict__ w1, const float* __restrict__ b1,
    const float* __restrict__ w2, const float* __restrict__ b2)
{
    extern __shared__ char sm[];
    const uint32_t smb = smem_u32(sm);
    const int tid = threadIdx.x, lane = tid & 31, wid = tid >> 5;
    const int wm = wid & 1, wn = wid >> 1;
    const int m0 = blockIdx.x * 128, f = blockIdx.y;

    float acc[4][8][4];
#pragma unroll
    for (int a = 0; a < 4; a++)
#pragma unroll
        for (int b = 0; b < 8; b++)
#pragma unroll
            for (int c = 0; c < 4; c++) acc[a][b][c] = 0.f;

    const int grow = tid & 127, gseg = tid >> 7;   // row, k-half (16 each)
    const float xv = x[(m0 + grow) * FN + f];
    const float* __restrict__ w1f = w1 + f * HN;
    const float* __restrict__ b1f = b1 + f * HN;
    const float* __restrict__ w2f = w2 + (size_t)f * HN * HN;

    float4 rb[8];
#define LOAD_B2(kt) do { \
    _Pragma("unroll") \
    for (int i = 0; i < 8; i++) { \
        const int u = tid + 256 * i; \
        const int row = u >> 6, cu = u & 63; \
        rb[i] = *(const float4*)(w2f + (size_t)((kt) * 32 + row) * HN + cu * 4); \
    } } while (0)

    LOAD_B2(0);
    for (int kt = 0; kt < 8; kt++) {
        const int k0 = kt * 32;
        // generate + split A: 128 rows x 32 k
#pragma unroll
        for (int oct = 0; oct < 2; oct++) {
            const int kk = k0 + gseg * 16 + oct * 8;
            float4 wa = *(const float4*)(w1f + kk),  wb = *(const float4*)(w1f + kk + 4);
            float4 ca = *(const float4*)(b1f + kk),  cb = *(const float4*)(b1f + kk + 4);
            float v[8] = { eluf(xv*wa.x+ca.x), eluf(xv*wa.y+ca.y), eluf(xv*wa.z+ca.z), eluf(xv*wa.w+ca.w),
                           eluf(xv*wb.x+cb.x), eluf(xv*wb.y+cb.y), eluf(xv*wb.z+cb.z), eluf(xv*wb.w+cb.w) };
            uint4 H = { pack_hi2(v[0],v[1]), pack_hi2(v[2],v[3]), pack_hi2(v[4],v[5]), pack_hi2(v[6],v[7]) };
            uint4 L = { pack_lo2(v[0],v[1]), pack_lo2(v[2],v[3]), pack_lo2(v[4],v[5]), pack_lo2(v[6],v[7]) };
            const uint32_t o = grow * AST + gseg * 32 + oct * 16;
            *(uint4*)(sm + o) = H;
            *(uint4*)(sm + S_AL + o) = L;
        }
        // stage B regs -> smem
#pragma unroll
        for (int i = 0; i < 8; i++) {
            const int u = tid + 256 * i;
            const int row = u >> 6, cu = u & 63;
            const uint32_t o = row * BST + cu * 8;
            *(uint2*)(sm + S_BH + o) = make_uint2(pack_hi2(rb[i].x, rb[i].y), pack_hi2(rb[i].z, rb[i].w));
            *(uint2*)(sm + S_BL + o) = make_uint2(pack_lo2(rb[i].x, rb[i].y), pack_lo2(rb[i].z, rb[i].w));
        }
        __syncthreads();
        if (kt + 1 < 8) LOAD_B2(kt + 1);
        ktile1(smb, smb + S_AL, smb + S_BH, smb + S_BL, acc, lane, wm, wn);
        __syncthreads();
    }
#undef LOAD_B2
    // epilogue: + b2, store fp32 g_h1[f][m][n]
#pragma unroll
    for (int mt = 0; mt < 4; mt++)
#pragma unroll
        for (int j = 0; j < 8; j++) {
            const int n  = wn * 64 + j * 8 + (lane & 3) * 2;
            const int r0 = wm * 64 + mt * 16 + (lane >> 2);
            float2 bb = *(const float2*)(b2 + f * HN + n);
            float2 o0 = { acc[mt][j][0] + bb.x, acc[mt][j][1] + bb.y };
            float2 o1 = { acc[mt][j][2] + bb.x, acc[mt][j][3] + bb.y };
            *(float2*)(g_h1 + ((size_t)f * BTN + m0 + r0) * HN + n) = o0;
            *(float2*)(g_h1 + ((size_t)f * BTN + m0 + r0 + 8) * HN + n) = o1;
        }
}

// ---------------------------------------------------------------------------
// k_glu: GLU + skip + LN fused, elementwise. One warp per (f, bt) row.
// stk[m][f*H+h] = LN( sig(pg+bg)*(pf+bf) + x*ws + bs )
// ---------------------------------------------------------------------------
__global__ __launch_bounds__(256) void k_glu(
    const float* __restrict__ x,
    const float* __restrict__ bg, const float* __restrict__ bf_,
    const float* __restrict__ ws, const float* __restrict__ bs,
    const float* __restrict__ gamma, const float* __restrict__ beta)
{
    const int lane = threadIdx.x & 31;
    const int m = blockIdx.x * 8 + (threadIdx.x >> 5);
    const int f = blockIdx.y;
    const float* __restrict__ pg = g_pg + ((size_t)f * BTN + m) * HN;
    const float* __restrict__ pf = g_pf + ((size_t)f * BTN + m) * HN;
    const float xv = x[m * FN + f];
    float v[8];
    float s = 0.f;
#pragma unroll
    for (int i = 0; i < 8; i++) {
        const int h = i * 32 + lane;
        const float g  = pg[h] + bg[f * HN + h];
        const float vv = pf[h] + bf_[f * HN + h];
        const float pre = sigf(g) * vv + xv * ws[f * HN + h] + bs[f * HN + h];
        v[i] = pre; s += pre;
    }
#pragma unroll
    for (int o = 16; o > 0; o >>= 1) s += __shfl_xor_sync(0xffffffffu, s, o);
    const float mean = s * (1.f / 256.f);
    float q = 0.f;
#pragma unroll
    for (int i = 0; i < 8; i++) { const float d = v[i] - mean; q += d * d; }
#pragma unroll
    for (int o = 16; o > 0; o >>= 1) q += __shfl_xor_sync(0xffffffffu, q, o);
    const float rstd = rsqrtf(q * (1.f / 256.f) + 1e-5f);
    float* __restrict__ op = g_stk + (size_t)m * FHN + f * HN;
#pragma unroll
    for (int i = 0; i < 8; i++) {
        const int h = i * 32 + lane;
        op[h] = (v[i] - mean) * rstd * gamma[f * HN + h] + beta[f * HN + h];
    }
}

// ---------------------------------------------------------------------------
__global__ __launch_bounds__(256) void k_sres(
    const float* __restrict__ ssw, const float* __restrict__ ssb)
{
    const int lane = threadIdx.x & 31;
    const int m    = blockIdx.x * 8 + (threadIdx.x >> 5);
    const float* __restrict__ a = g_stk + (size_t)m * FHN;
    float acc = 0.f;
#pragma unroll 4
    for (int k = 0; k < FHN; k += 4) {
        float4 av = *(const float4*)(a + k);
        acc += av.x * ssw[(k + 0) * FN + lane];
        acc += av.y * ssw[(k + 1) * FN + lane];
        acc += av.z * ssw[(k + 2) * FN + lane];
        acc += av.w * ssw[(k + 3) * FN + lane];
    }
    g_sres[m * FN + lane] = acc + ssb[lane];
}

// ---------------------------------------------------------------------------
__global__ __launch_bounds__(256) void k_sel(
    const float* __restrict__ sw2, const float* __restrict__ sb2,
    const float* __restrict__ swg, const float* __restrict__ sbg,
    const float* __restrict__ swf, const float* __restrict__ sbf,
    const float* __restrict__ sgm, const float* __restrict__ sbt)
{
    const int lane = threadIdx.x & 31;
    const int m    = blockIdx.x * 8 + (threadIdx.x >> 5);
    const float* __restrict__ sh = g_sh + (size_t)m * HN;
    float shv[8];
#pragma unroll
    for (int i = 0; i < 8; i++) shv[i] = sh[i * 32 + lane];
    float acc = sb2[lane];
#pragma unroll 8
    for (int h = 0; h < HN; h++) {
        float s = __shfl_sync(0xffffffffu, shv[h >> 5], h & 31);
        acc += s * sw2[h * FN + lane];
    }
    float ag = sbg[lane], af = sbf[lane];
#pragma unroll
    for (int i = 0; i < FN; i++) {
        float s = __shfl_sync(0xffffffffu, acc, i);
        ag += s * swg[i * FN + lane];
        af += s * swf[i * FN + lane];
    }
    const float pre = g_sres[m * FN + lane] + sigf(ag) * af;
    float s1 = pre;
#pragma unroll
    for (int o = 16; o > 0; o >>= 1) s1 += __shfl_xor_sync(0xffffffffu, s1, o);
    const float mean = s1 * (1.f / 32.f);
    const float d = pre - mean;
    float q = d * d;
#pragma unroll
    for (int o = 16; o > 0; o >>= 1) q += __shfl_xor_sync(0xffffffffu, q, o);
    const float y = d * rsqrtf(q * (1.f / 32.f) + 1e-5f) * sgm[lane] + sbt[lane];
    float mx = y;
#pragma unroll
    for (int o = 16; o > 0; o >>= 1) mx = fmaxf(mx, __shfl_xor_sync(0xffffffffu, mx, o));
    const float e = __expf(y - mx);
    float se = e;
#pragma unroll
    for (int o = 16; o > 0; o >>= 1) se += __shfl_xor_sync(0xffffffffu, se, o);
    g_wts[m * FN + lane] = e / se;
}

// ---------------------------------------------------------------------------
__global__ __launch_bounds__(256) void k_out(float* __restrict__ out)
{
    const int m = blockIdx.x * 4 + (threadIdx.x >> 6);
    const int c = threadIdx.x & 63;
    const float4* __restrict__ sp = (const float4*)(g_stk + (size_t)m * FHN);
    const float* __restrict__ wp = g_wts + m * FN;
    float4 acc = make_float4(0.f, 0.f, 0.f, 0.f);
#pragma unroll
    for (int f = 0; f < FN; f++) {
        const float w = wp[f];
        float4 v = sp[f * 64 + c];
        acc.x += w * v.x; acc.y += w * v.y; acc.z += w * v.z; acc.w += w * v.w;
    }
    ((float4*)out)[(size_t)m * 64 + c] = acc;
}

// ---------------------------------------------------------------------------
extern "C" void kernel_launch(void* const* d_in, const int* in_sizes, int n_in,
                              void* d_out, int out_size)
{
    const float* x    = (const float*)d_in[0];
    const float* w1   = (const float*)d_in[1];
    const float* b1   = (const float*)d_in[2];
    const float* w2   = (const float*)d_in[3];
    const float* b2   = (const float*)d_in[4];
    const float* wg   = (const float*)d_in[5];
    const float* bg   = (const float*)d_in[6];
    const float* wf   = (const float*)d_in[7];
    const float* bf   = (const float*)d_in[8];
    const float* gamma= (const float*)d_in[9];
    const float* beta = (const float*)d_in[10];
    const float* ws   = (const float*)d_in[11];
    const float* bs   = (const float*)d_in[12];
    const float* sw1  = (const float*)d_in[13];
    const float* sb1  = (const float*)d_in[14];
    const float* sw2  = (const float*)d_in[15];
    const float* sb2  = (const float*)d_in[16];
    const float* swg  = (const float*)d_in[17];
    const float* sbg  = (const float*)d_in[18];
    const float* swf  = (const float*)d_in[19];
    const float* sbf  = (const float*)d_in[20];
    const float* sgm  = (const float*)d_in[21];
    const float* sbt  = (const float*)d_in[22];
    const float* ssw  = (const float*)d_in[23];
    const float* ssb  = (const float*)d_in[24];
    float* out = (float*)d_out;

    cudaFuncSetAttribute(k_hA,   cudaFuncAttributeMaxDynamicSharedMemorySize, SM_S);
    cudaFuncSetAttribute(k_hmma, cudaFuncAttributeMaxDynamicSharedMemorySize, SM_S);

    float *h1p, *pgp, *pfp, *stkp, *shp;
    cudaGetSymbolAddress((void**)&h1p,  g_h1);
    cudaGetSymbolAddress((void**)&pgp,  g_pg);
    cudaGetSymbolAddress((void**)&pfp,  g_pf);
    cudaGetSymbolAddress((void**)&stkp, g_stk);
    cudaGetSymbolAddress((void**)&shp,  g_sh);

    const size_t FS = (size_t)BTN * HN;   // per-f slab of h1/pg/pf
    const size_t WS = (size_t)HN * HN;    // per-f weight slab

    k_hA  <<<dim3(BTN / 128, FN), 256, SM_S>>>(x, w1, b1, w2, b2);
    k_hmma<<<dim3(BTN / 128, FN), 256, SM_S>>>(h1p, FS, HN, wg, WS, nullptr, pgp, FS, HN, 8, 0);
    k_hmma<<<dim3(BTN / 128, FN), 256, SM_S>>>(h1p, FS, HN, wf, WS, nullptr, pfp, FS, HN, 8, 0);
    k_glu <<<dim3(BTN / 8, FN), 256>>>(x, bg, bf, ws, bs, gamma, beta);
    k_hmma<<<dim3(BTN / 128, 1), 256, SM_S>>>(stkp, 0, FHN, sw1, 0, sb1, shp, 0, HN, FHN / 32, 1);
    k_sres<<<BTN / 8, 256>>>(ssw, ssb);
    k_sel <<<BTN / 8, 256>>>(sw2, sb2, swg, sbg, swf, sbf, sgm, sbt);
    k_out <<<BTN / 4, 256>>>(out);
}

// round 7
// speedup vs baseline: 2.0858x; 1.1686x over previous
#include <cuda_runtime.h>
#include <cuda_bf16.h>
#include <math.h>
#include <stdint.h>

#define BTN 16384
#define FN  32
#define HN  256
#define FHN 8192

// ---------------- scratch ----------------
__device__ float g_cg [(size_t)FN * HN * HN];  // w2@wg
__device__ float g_cf [(size_t)FN * HN * HN];  // w2@wf
__device__ float g_cbg[FN * HN];               // b2@wg + bg
__device__ float g_cbf[FN * HN];               // b2@wf + bf
__device__ float g_sg [(size_t)BTN * FN * HN]; // sigmoid(gate) [f][bt][h]
__device__ float g_stk[(size_t)BTN * FN * HN]; // [bt][f*H+h]
__device__ float g_sh [(size_t)BTN * HN];
__device__ float g_sres[BTN * FN];
__device__ float g_wts [BTN * FN];

__device__ __forceinline__ float eluf(float z) { return z > 0.f ? z : (__expf(z) - 1.f); }
__device__ __forceinline__ float sigf(float z) { return 1.f / (1.f + __expf(-z)); }

__device__ __forceinline__ uint32_t smem_u32(const void* p) {
    uint32_t a;
    asm("{ .reg .u64 t; cvta.to.shared.u64 t, %1; cvt.u32.u64 %0, t; }" : "=r"(a) : "l"(p));
    return a;
}
__device__ __forceinline__ void ldsm_x4(uint32_t* r, uint32_t a) {
    asm volatile("ldmatrix.sync.aligned.m8n8.x4.shared.b16 {%0,%1,%2,%3}, [%4];"
                 : "=r"(r[0]), "=r"(r[1]), "=r"(r[2]), "=r"(r[3]) : "r"(a));
}
__device__ __forceinline__ void ldsm_x4t(uint32_t* r, uint32_t a) {
    asm volatile("ldmatrix.sync.aligned.m8n8.x4.trans.shared.b16 {%0,%1,%2,%3}, [%4];"
                 : "=r"(r[0]), "=r"(r[1]), "=r"(r[2]), "=r"(r[3]) : "r"(a));
}
__device__ __forceinline__ void mmab(float* d, const uint32_t* a, uint32_t b0, uint32_t b1) {
    asm volatile("mma.sync.aligned.m16n8k16.row.col.f32.bf16.bf16.f32 "
                 "{%0,%1,%2,%3}, {%4,%5,%6,%7}, {%8,%9}, {%0,%1,%2,%3};"
                 : "+f"(d[0]), "+f"(d[1]), "+f"(d[2]), "+f"(d[3])
                 : "r"(a[0]), "r"(a[1]), "r"(a[2]), "r"(a[3]), "r"(b0), "r"(b1));
}
__device__ __forceinline__ uint32_t pack_hi2(float v0, float v1) {
    __nv_bfloat162 p = __floats2bfloat162_rn(v0, v1);
    return *(uint32_t*)&p;
}
__device__ __forceinline__ uint32_t pack_lo2(float v0, float v1) {
    float r0 = v0 - __bfloat162float(__float2bfloat16_rn(v0));
    float r1 = v1 - __bfloat162float(__float2bfloat16_rn(v1));
    __nv_bfloat162 p = __floats2bfloat162_rn(r0, r1);
    return *(uint32_t*)&p;
}

#define AST 80u
#define BST 528u
#define S_AL  10240
#define S_BH  20480
#define S_BL  37376
#define SM_S  54272

// one 32-wide k-chunk: C += (Ah+Al) @ (Bh+Bl) [3-term], M=128, N=256
__device__ __forceinline__ void ktile1(
    uint32_t aH, uint32_t aL, uint32_t bH, uint32_t bL,
    float (&acc)[4][8][4], int lane, int wm, int wn)
{
#pragma unroll
    for (int k16 = 0; k16 < 32; k16 += 16) {
        uint32_t Ah[4][4], Al[4][4];
#pragma unroll
        for (int mt = 0; mt < 4; mt++) {
            uint32_t ro = (uint32_t)(wm * 64 + mt * 16 + (lane & 15)) * AST
                        + (uint32_t)(k16 + ((lane >> 4) << 3)) * 2u;
            ldsm_x4(Ah[mt], aH + ro);
            ldsm_x4(Al[mt], aL + ro);
        }
        const int mat = lane >> 3;
#pragma unroll
        for (int nq = 0; nq < 4; nq++) {
            const int nb = wn * 64 + nq * 16;
            uint32_t bo = (uint32_t)(k16 + (mat & 1) * 8 + (lane & 7)) * BST
                        + (uint32_t)(nb + (mat >> 1) * 8) * 2u;
            uint32_t bh[4], bl[4];
            ldsm_x4t(bh, bH + bo);
            ldsm_x4t(bl, bL + bo);
#pragma unroll
            for (int mt = 0; mt < 4; mt++) {
                mmab(acc[mt][nq*2+0], Ah[mt], bh[0], bh[1]);
                mmab(acc[mt][nq*2+1], Ah[mt], bh[2], bh[3]);
                mmab(acc[mt][nq*2+0], Al[mt], bh[0], bh[1]);
                mmab(acc[mt][nq*2+1], Al[mt], bh[2], bh[3]);
                mmab(acc[mt][nq*2+0], Ah[mt], bl[0], bl[1]);
                mmab(acc[mt][nq*2+1], Ah[mt], bl[2], bl[3]);
            }
        }
    }
}

// ---------------------------------------------------------------------------
// Generic HMMA GEMM (validated): C[f] = doElu ? elu(A[f]@B[f]+bias) : A[f]@B[f]+bias
// ---------------------------------------------------------------------------
__global__ void __launch_bounds__(256, 1) k_hmma(
    const float* __restrict__ A, size_t aF, int lda,
    const float* __restrict__ B, size_t bF,
    const float* __restrict__ bias, float* __restrict__ C, size_t cF, int ldc,
    int kTiles, int doElu)
{
    extern __shared__ char sm[];
    const uint32_t smb = smem_u32(sm);
    const int tid = threadIdx.x, lane = tid & 31, wid = tid >> 5;
    const int wm = wid & 1, wn = wid >> 1;
    const int m0 = blockIdx.x * 128, f = blockIdx.y;
    A += aF * f; B += bF * f; C += cF * f;

    float acc[4][8][4];
#pragma unroll
    for (int a = 0; a < 4; a++)
#pragma unroll
        for (int b = 0; b < 8; b++)
#pragma unroll
            for (int c = 0; c < 4; c++) acc[a][b][c] = 0.f;

    float4 ra[4], rb[8];
#define LOAD_A(kt) do { \
    _Pragma("unroll") \
    for (int i = 0; i < 4; i++) { \
        const int u = tid + 256 * i; \
        const int row = u >> 3, cu = u & 7; \
        ra[i] = *(const float4*)(A + (size_t)(m0 + row) * lda + (kt) * 32 + cu * 4); \
    } } while (0)
#define LOAD_B(kt) do { \
    _Pragma("unroll") \
    for (int i = 0; i < 8; i++) { \
        const int u = tid + 256 * i; \
        const int row = u >> 6, cu = u & 63; \
        rb[i] = *(const float4*)(B + (size_t)((kt) * 32 + row) * HN + cu * 4); \
    } } while (0)

    LOAD_A(0); LOAD_B(0);
    for (int kt = 0; kt < kTiles; kt++) {
#pragma unroll
        for (int i = 0; i < 4; i++) {
            const int u = tid + 256 * i;
            const int row = u >> 3, cu = u & 7;
            const uint32_t o = row * AST + cu * 8;
            *(uint2*)(sm + o)        = make_uint2(pack_hi2(ra[i].x, ra[i].y), pack_hi2(ra[i].z, ra[i].w));
            *(uint2*)(sm + S_AL + o) = make_uint2(pack_lo2(ra[i].x, ra[i].y), pack_lo2(ra[i].z, ra[i].w));
        }
#pragma unroll
        for (int i = 0; i < 8; i++) {
            const int u = tid + 256 * i;
            const int row = u >> 6, cu = u & 63;
            const uint32_t o = row * BST + cu * 8;
            *(uint2*)(sm + S_BH + o) = make_uint2(pack_hi2(rb[i].x, rb[i].y), pack_hi2(rb[i].z, rb[i].w));
            *(uint2*)(sm + S_BL + o) = make_uint2(pack_lo2(rb[i].x, rb[i].y), pack_lo2(rb[i].z, rb[i].w));
        }
        __syncthreads();
        if (kt + 1 < kTiles) { LOAD_A(kt + 1); LOAD_B(kt + 1); }
        ktile1(smb, smb + S_AL, smb + S_BH, smb + S_BL, acc, lane, wm, wn);
        __syncthreads();
    }
#undef LOAD_A
#undef LOAD_B
#pragma unroll
    for (int mt = 0; mt < 4; mt++)
#pragma unroll
        for (int j = 0; j < 8; j++) {
            const int n  = wn * 64 + j * 8 + (lane & 3) * 2;
            const int r0 = wm * 64 + mt * 16 + (lane >> 2);
            float2 bb = bias ? *(const float2*)(bias + n) : make_float2(0.f, 0.f);
            float v0 = acc[mt][j][0] + bb.x, v1 = acc[mt][j][1] + bb.y;
            float v2 = acc[mt][j][2] + bb.x, v3 = acc[mt][j][3] + bb.y;
            if (doElu) { v0 = eluf(v0); v1 = eluf(v1); v2 = eluf(v2); v3 = eluf(v3); }
            *(float2*)(C + (size_t)(m0 + r0) * ldc + n)     = make_float2(v0, v1);
            *(float2*)(C + (size_t)(m0 + r0 + 8) * ldc + n) = make_float2(v2, v3);
        }
}

// ---------------------------------------------------------------------------
// k_bias: cbg = b2@wg + bg (y=0) ; cbf = b2@wf + bf (y=1)
// ---------------------------------------------------------------------------
__global__ __launch_bounds__(256) void k_bias(
    const float* __restrict__ b2, const float* __restrict__ wg, const float* __restrict__ wf,
    const float* __restrict__ bg, const float* __restrict__ bf_)
{
    const int f = blockIdx.x, n = threadIdx.x;
    const float* W  = (blockIdx.y == 0) ? wg : wf;
    const float* bb = (blockIdx.y == 0) ? bg : bf_;
    float* out = (blockIdx.y == 0) ? g_cbg : g_cbf;
    float acc = bb[f * HN + n];
    const float* b2f_ = b2 + f * HN;
    const float* Wf_  = W + (size_t)f * HN * HN + n;
#pragma unroll 8
    for (int k = 0; k < HN; k++) acc += b2f_[k] * Wf_[(size_t)k * HN];
    out[f * HN + n] = acc;
}

// ---------------------------------------------------------------------------
// A-generation mainloop shared by gate/value kernels (h0 = elu(x*w1+b1) on the fly,
// B register-prefetched from a per-f 256x256 fp32 matrix).
// ---------------------------------------------------------------------------
#define GEN_MAINLOOP(Bmat)                                                           \
    const int grow = tid & 127, gseg = tid >> 7;                                     \
    const float xv = x[(m0 + grow) * FN + f];                                        \
    const float* __restrict__ w1f = w1 + f * HN;                                     \
    const float* __restrict__ b1f = b1 + f * HN;                                     \
    const float* __restrict__ Bf = (Bmat) + (size_t)f * HN * HN;                     \
    float4 rb[8];                                                                    \
    _Pragma("unroll")                                                                \
    for (int i = 0; i < 8; i++) {                                                    \
        const int u = tid + 256 * i;                                                 \
        const int row = u >> 6, cu = u & 63;                                         \
        rb[i] = *(const float4*)(Bf + (size_t)row * HN + cu * 4);                    \
    }                                                                                \
    for (int kt = 0; kt < 8; kt++) {                                                 \
        const int k0 = kt * 32;                                                      \
        _Pragma("unroll")                                                            \
        for (int oct = 0; oct < 2; oct++) {                                          \
            const int kk = k0 + gseg * 16 + oct * 8;                                 \
            float4 wa = *(const float4*)(w1f + kk),  wb = *(const float4*)(w1f + kk + 4); \
            float4 ca = *(const float4*)(b1f + kk),  cb = *(const float4*)(b1f + kk + 4); \
            float v[8] = { eluf(xv*wa.x+ca.x), eluf(xv*wa.y+ca.y), eluf(xv*wa.z+ca.z), eluf(xv*wa.w+ca.w), \
                           eluf(xv*wb.x+cb.x), eluf(xv*wb.y+cb.y), eluf(xv*wb.z+cb.z), eluf(xv*wb.w+cb.w) }; \
            uint4 H = { pack_hi2(v[0],v[1]), pack_hi2(v[2],v[3]), pack_hi2(v[4],v[5]), pack_hi2(v[6],v[7]) }; \
            uint4 L = { pack_lo2(v[0],v[1]), pack_lo2(v[2],v[3]), pack_lo2(v[4],v[5]), pack_lo2(v[6],v[7]) }; \
            const uint32_t o = grow * AST + gseg * 32 + oct * 16;                    \
            *(uint4*)(sm + o) = H;                                                   \
            *(uint4*)(sm + S_AL + o) = L;                                            \
        }                                                                            \
        _Pragma("unroll")                                                            \
        for (int i = 0; i < 8; i++) {                                                \
            const int u = tid + 256 * i;                                             \
            const int row = u >> 6, cu = u & 63;                                     \
            const uint32_t o = row * BST + cu * 8;                                   \
            *(uint2*)(sm + S_BH + o) = make_uint2(pack_hi2(rb[i].x, rb[i].y), pack_hi2(rb[i].z, rb[i].w)); \
            *(uint2*)(sm + S_BL + o) = make_uint2(pack_lo2(rb[i].x, rb[i].y), pack_lo2(rb[i].z, rb[i].w)); \
        }                                                                            \
        __syncthreads();                                                             \
        if (kt + 1 < 8) {                                                            \
            _Pragma("unroll")                                                        \
            for (int i = 0; i < 8; i++) {                                            \
                const int u = tid + 256 * i;                                         \
                const int row = u >> 6, cu = u & 63;                                 \
                rb[i] = *(const float4*)(Bf + (size_t)((kt + 1) * 32 + row) * HN + cu * 4); \
            }                                                                        \
        }                                                                            \
        ktile1(smb, smb + S_AL, smb + S_BH, smb + S_BL, acc, lane, wm, wn);          \
        __syncthreads();                                                             \
    }

// ---------------------------------------------------------------------------
// k_gate: g_sg[f][m][h] = sigmoid(h0 @ Cg + cbg)
// ---------------------------------------------------------------------------
__global__ void __launch_bounds__(256, 1) k_gate(
    const float* __restrict__ x, const float* __restrict__ w1, const float* __restrict__ b1)
{
    extern __shared__ char sm[];
    const uint32_t smb = smem_u32(sm);
    const int tid = threadIdx.x, lane = tid & 31, wid = tid >> 5;
    const int wm = wid & 1, wn = wid >> 1;
    const int m0 = blockIdx.x * 128, f = blockIdx.y;

    float acc[4][8][4];
#pragma unroll
    for (int a = 0; a < 4; a++)
#pragma unroll
        for (int b = 0; b < 8; b++)
#pragma unroll
            for (int c = 0; c < 4; c++) acc[a][b][c] = 0.f;

    GEN_MAINLOOP(g_cg)

#pragma unroll
    for (int mt = 0; mt < 4; mt++)
#pragma unroll
        for (int j = 0; j < 8; j++) {
            const int n  = wn * 64 + j * 8 + (lane & 3) * 2;
            const int r0 = wm * 64 + mt * 16 + (lane >> 2);
            float2 bb = *(const float2*)(g_cbg + f * HN + n);
            float2 o0 = { sigf(acc[mt][j][0] + bb.x), sigf(acc[mt][j][1] + bb.y) };
            float2 o1 = { sigf(acc[mt][j][2] + bb.x), sigf(acc[mt][j][3] + bb.y) };
            *(float2*)(g_sg + ((size_t)f * BTN + m0 + r0) * HN + n) = o0;
            *(float2*)(g_sg + ((size_t)f * BTN + m0 + r0 + 8) * HN + n) = o1;
        }
}

// ---------------------------------------------------------------------------
// k_val: value GEMM + GLU + skip + LN fused; writes g_stk[m][f*H+h].
// ---------------------------------------------------------------------------
__global__ void __launch_bounds__(256, 1) k_val(
    const float* __restrict__ x, const float* __restrict__ w1, const float* __restrict__ b1,
    const float* __restrict__ ws, const float* __restrict__ bs,
    const float* __restrict__ gamma, const float* __restrict__ beta)
{
    extern __shared__ char sm[];
    const uint32_t smb = smem_u32(sm);
    const int tid = threadIdx.x, lane = tid & 31, wid = tid >> 5;
    const int wm = wid & 1, wn = wid >> 1;
    const int m0 = blockIdx.x * 128, f = blockIdx.y;

    float acc[4][8][4];
#pragma unroll
    for (int a = 0; a < 4; a++)
#pragma unroll
        for (int b = 0; b < 8; b++)
#pragma unroll
            for (int c = 0; c < 4; c++) acc[a][b][c] = 0.f;

    GEN_MAINLOOP(g_cf)

    // --- epilogue: GLU + skip into acc (in place) ---
#pragma unroll
    for (int mt = 0; mt < 4; mt++) {
        const int rA = m0 + wm * 64 + mt * 16 + (lane >> 2);
        const float xa = x[rA * FN + f];
        const float xb = x[(rA + 8) * FN + f];
#pragma unroll
        for (int j = 0; j < 8; j++) {
            const int n = wn * 64 + j * 8 + (lane & 3) * 2;
            float2 cb  = *(const float2*)(g_cbf + f * HN + n);
            float2 wsv = *(const float2*)(ws + f * HN + n);
            float2 bsv = *(const float2*)(bs + f * HN + n);
            float2 sg0 = *(const float2*)(g_sg + ((size_t)f * BTN + rA) * HN + n);
            float2 sg1 = *(const float2*)(g_sg + ((size_t)f * BTN + rA + 8) * HN + n);
            acc[mt][j][0] = sg0.x * (acc[mt][j][0] + cb.x) + xa * wsv.x + bsv.x;
            acc[mt][j][1] = sg0.y * (acc[mt][j][1] + cb.y) + xa * wsv.y + bsv.y;
            acc[mt][j][2] = sg1.x * (acc[mt][j][2] + cb.x) + xb * wsv.x + bsv.x;
            acc[mt][j][3] = sg1.y * (acc[mt][j][3] + cb.y) + xb * wsv.y + bsv.y;
        }
    }
    // --- LN: partial sums per row across lane&3 (shfl) then wn (smem) ---
    float2* part = (float2*)sm;   // [128 rows][4 wn]
#pragma unroll
    for (int mt = 0; mt < 4; mt++) {
        float s0 = 0.f, q0 = 0.f, s1 = 0.f, q1 = 0.f;
#pragma unroll
        for (int j = 0; j < 8; j++) {
            s0 += acc[mt][j][0] + acc[mt][j][1];
            q0 += acc[mt][j][0] * acc[mt][j][0] + acc[mt][j][1] * acc[mt][j][1];
            s1 += acc[mt][j][2] + acc[mt][j][3];
            q1 += acc[mt][j][2] * acc[mt][j][2] + acc[mt][j][3] * acc[mt][j][3];
        }
#pragma unroll
        for (int o = 1; o <= 2; o <<= 1) {
            s0 += __shfl_xor_sync(0xffffffffu, s0, o);
            q0 += __shfl_xor_sync(0xffffffffu, q0, o);
            s1 += __shfl_xor_sync(0xffffffffu, s1, o);
            q1 += __shfl_xor_sync(0xffffffffu, q1, o);
        }
        if ((lane & 3) == 0) {
            const int r0 = wm * 64 + mt * 16 + (lane >> 2);
            part[r0 * 4 + wn]       = make_float2(s0, q0);
            part[(r0 + 8) * 4 + wn] = make_float2(s1, q1);
        }
    }
    __syncthreads();
#pragma unroll
    for (int mt = 0; mt < 4; mt++) {
        const int r0 = wm * 64 + mt * 16 + (lane >> 2);
        float2 p0 = part[r0 * 4 + 0], p1 = part[r0 * 4 + 1];
        float2 p2 = part[r0 * 4 + 2], p3 = part[r0 * 4 + 3];
        float sA = p0.x + p1.x + p2.x + p3.x, qA = p0.y + p1.y + p2.y + p3.y;
        p0 = part[(r0 + 8) * 4 + 0]; p1 = part[(r0 + 8) * 4 + 1];
        p2 = part[(r0 + 8) * 4 + 2]; p3 = part[(r0 + 8) * 4 + 3];
        float sB = p0.x + p1.x + p2.x + p3.x, qB = p0.y + p1.y + p2.y + p3.y;
        const float mA = sA * (1.f / 256.f);
        float vA = qA * (1.f / 256.f) - mA * mA; vA = vA > 0.f ? vA : 0.f;
        const float rA_ = rsqrtf(vA + 1e-5f);
        const float mB = sB * (1.f / 256.f);
        float vB = qB * (1.f / 256.f) - mB * mB; vB = vB > 0.f ? vB : 0.f;
        const float rB_ = rsqrtf(vB + 1e-5f);
        float* o0p = g_stk + (size_t)(m0 + r0) * FHN + f * HN;
        float* o1p = g_stk + (size_t)(m0 + r0 + 8) * FHN + f * HN;
#pragma unroll
        for (int j = 0; j < 8; j++) {
            const int n = wn * 64 + j * 8 + (lane & 3) * 2;
            float2 gm = *(const float2*)(gamma + f * HN + n);
            float2 bt = *(const float2*)(beta + f * HN + n);
            *(float2*)(o0p + n) = make_float2((acc[mt][j][0] - mA) * rA_ * gm.x + bt.x,
                                              (acc[mt][j][1] - mA) * rA_ * gm.y + bt.y);
            *(float2*)(o1p + n) = make_float2((acc[mt][j][2] - mB) * rB_ * gm.x + bt.x,
                                              (acc[mt][j][3] - mB) * rB_ * gm.y + bt.y);
        }
    }
}

// ---------------------------------------------------------------------------
__global__ __launch_bounds__(256) void k_sres(
    const float* __restrict__ ssw, const float* __restrict__ ssb)
{
    const int lane = threadIdx.x & 31;
    const int m    = blockIdx.x * 8 + (threadIdx.x >> 5);
    const float* __restrict__ a = g_stk + (size_t)m * FHN;
    float acc = 0.f;
#pragma unroll 4
    for (int k = 0; k < FHN; k += 4) {
        float4 av = *(const float4*)(a + k);
        acc += av.x * ssw[(k + 0) * FN + lane];
        acc += av.y * ssw[(k + 1) * FN + lane];
        acc += av.z * ssw[(k + 2) * FN + lane];
        acc += av.w * ssw[(k + 3) * FN + lane];
    }
    g_sres[m * FN + lane] = acc + ssb[lane];
}

// ---------------------------------------------------------------------------
__global__ __launch_bounds__(256) void k_sel(
    const float* __restrict__ sw2, const float* __restrict__ sb2,
    const float* __restrict__ swg, const float* __restrict__ sbg,
    const float* __restrict__ swf, const float* __restrict__ sbf,
    const float* __restrict__ sgm, const float* __restrict__ sbt)
{
    const int lane = threadIdx.x & 31;
    const int m    = blockIdx.x * 8 + (threadIdx.x >> 5);
    const float* __restrict__ sh = g_sh + (size_t)m * HN;
    float shv[8];
#pragma unroll
    for (int i = 0; i < 8; i++) shv[i] = sh[i * 32 + lane];
    float acc = sb2[lane];
#pragma unroll 8
    for (int h = 0; h < HN; h++) {
        float s = __shfl_sync(0xffffffffu, shv[h >> 5], h & 31);
        acc += s * sw2[h * FN + lane];
    }
    float ag = sbg[lane], af = sbf[lane];
#pragma unroll
    for (int i = 0; i < FN; i++) {
        float s = __shfl_sync(0xffffffffu, acc, i);
        ag += s * swg[i * FN + lane];
        af += s * swf[i * FN + lane];
    }
    const float pre = g_sres[m * FN + lane] + sigf(ag) * af;
    float s1 = pre;
#pragma unroll
    for (int o = 16; o > 0; o >>= 1) s1 += __shfl_xor_sync(0xffffffffu, s1, o);
    const float mean = s1 * (1.f / 32.f);
    const float d = pre - mean;
    float q = d * d;
#pragma unroll
    for (int o = 16; o > 0; o >>= 1) q += __shfl_xor_sync(0xffffffffu, q, o);
    const float y = d * rsqrtf(q * (1.f / 32.f) + 1e-5f) * sgm[lane] + sbt[lane];
    float mx = y;
#pragma unroll
    for (int o = 16; o > 0; o >>= 1) mx = fmaxf(mx, __shfl_xor_sync(0xffffffffu, mx, o));
    const float e = __expf(y - mx);
    float se = e;
#pragma unroll
    for (int o = 16; o > 0; o >>= 1) se += __shfl_xor_sync(0xffffffffu, se, o);
    g_wts[m * FN + lane] = e / se;
}

// ---------------------------------------------------------------------------
__global__ __launch_bounds__(256) void k_out(float* __restrict__ out)
{
    const int m = blockIdx.x * 4 + (threadIdx.x >> 6);
    const int c = threadIdx.x & 63;
    const float4* __restrict__ sp = (const float4*)(g_stk + (size_t)m * FHN);
    const float* __restrict__ wp = g_wts + m * FN;
    float4 acc = make_float4(0.f, 0.f, 0.f, 0.f);
#pragma unroll
    for (int f = 0; f < FN; f++) {
        const float w = wp[f];
        float4 v = sp[f * 64 + c];
        acc.x += w * v.x; acc.y += w * v.y; acc.z += w * v.z; acc.w += w * v.w;
    }
    ((float4*)out)[(size_t)m * 64 + c] = acc;
}

// ---------------------------------------------------------------------------
extern "C" void kernel_launch(void* const* d_in, const int* in_sizes, int n_in,
                              void* d_out, int out_size)
{
    const float* x    = (const float*)d_in[0];
    const float* w1   = (const float*)d_in[1];
    const float* b1   = (const float*)d_in[2];
    const float* w2   = (const float*)d_in[3];
    const float* b2   = (const float*)d_in[4];
    const float* wg   = (const float*)d_in[5];
    const float* bg   = (const float*)d_in[6];
    const float* wf   = (const float*)d_in[7];
    const float* bf   = (const float*)d_in[8];
    const float* gamma= (const float*)d_in[9];
    const float* beta = (const float*)d_in[10];
    const float* ws   = (const float*)d_in[11];
    const float* bs   = (const float*)d_in[12];
    const float* sw1  = (const float*)d_in[13];
    const float* sb1  = (const float*)d_in[14];
    const float* sw2  = (const float*)d_in[15];
    const float* sb2  = (const float*)d_in[16];
    const float* swg  = (const float*)d_in[17];
    const float* sbg  = (const float*)d_in[18];
    const float* swf  = (const float*)d_in[19];
    const float* sbf  = (const float*)d_in[20];
    const float* sgm  = (const float*)d_in[21];
    const float* sbt  = (const float*)d_in[22];
    const float* ssw  = (const float*)d_in[23];
    const float* ssb  = (const float*)d_in[24];
    float* out = (float*)d_out;

    cudaFuncSetAttribute(k_hmma, cudaFuncAttributeMaxDynamicSharedMemorySize, SM_S);
    cudaFuncSetAttribute(k_gate, cudaFuncAttributeMaxDynamicSharedMemorySize, SM_S);
    cudaFuncSetAttribute(k_val,  cudaFuncAttributeMaxDynamicSharedMemorySize, SM_S);

    float *cgp, *cfp, *stkp, *shp;
    cudaGetSymbolAddress((void**)&cgp,  g_cg);
    cudaGetSymbolAddress((void**)&cfp,  g_cf);
    cudaGetSymbolAddress((void**)&stkp, g_stk);
    cudaGetSymbolAddress((void**)&shp,  g_sh);

    const size_t WS = (size_t)HN * HN;

    // weight-space fusion: Cg = w2@wg, Cf = w2@wf (per f)
    k_hmma<<<dim3(2, FN), 256, SM_S>>>(w2, WS, HN, wg, WS, nullptr, cgp, WS, HN, 8, 0);
    k_hmma<<<dim3(2, FN), 256, SM_S>>>(w2, WS, HN, wf, WS, nullptr, cfp, WS, HN, 8, 0);
    k_bias<<<dim3(FN, 2), 256>>>(b2, wg, wf, bg, bf);

    k_gate<<<dim3(BTN / 128, FN), 256, SM_S>>>(x, w1, b1);
    k_val <<<dim3(BTN / 128, FN), 256, SM_S>>>(x, w1, b1, ws, bs, gamma, beta);

    k_hmma<<<dim3(BTN / 128, 1), 256, SM_S>>>(stkp, 0, FHN, sw1, 0, sb1, shp, 0, HN, FHN / 32, 1);
    k_sres<<<BTN / 8, 256>>>(ssw, ssb);
    k_sel <<<BTN / 8, 256>>>(sw2, sb2, swg, sbg, swf, sbf, sgm, sbt);
    k_out <<<BTN / 4, 256>>>(out);
}